// round 1
// baseline (speedup 1.0000x reference)
#include <cuda_runtime.h>
#include <math.h>

#define BATCH 16
#define CIN   192
#define CHID  384
#define HEADS 8
#define HDIM  48
#define IMG   56
#define HW    3136        // 56*56
#define KS    7

// ---------------- scratch (device globals; no allocs) ----------------
__device__ float g_qWkT[HEADS * CIN];        // [h][D]
__device__ float g_biasq[HEADS];
__device__ float g_rpeexp[HEADS * 49];
__device__ float g_V[(size_t)BATCH * CHID * HW];       // 77 MB
__device__ float g_COSTE[(size_t)BATCH * HEADS * HW];  // 1.6 MB
__device__ float g_OUTPRE[(size_t)BATCH * CHID * HW];  // 77 MB

// ---------------- K0: prep (q normalize, fold into Wk, exp rpe) ------
__global__ void prep_kernel(const float* __restrict__ query,
                            const float* __restrict__ Wk,
                            const float* __restrict__ Wk_bias,
                            const float* __restrict__ rpe) {
    __shared__ float sq[CHID];
    __shared__ float snorm[HEADS];
    int tid = threadIdx.x;
    float inv = 1.0f / (sqrtf((float)HDIM) + 1e-6f);
    if (tid < CHID) sq[tid] = query[tid] * inv;
    __syncthreads();
    if (tid < HEADS) {
        float s = 0.f;
        for (int d = 0; d < HDIM; d++) { float v = sq[tid * HDIM + d]; s += v * v; }
        snorm[tid] = sqrtf(s) + 1e-6f;
    }
    __syncthreads();
    if (tid < CHID) sq[tid] = sq[tid] / snorm[tid / HDIM];
    __syncthreads();
    // qWkT[h][D] = sum_d q[h,d] * Wk[D, h*48+d]
    for (int e = tid; e < HEADS * CIN; e += blockDim.x) {
        int h = e / CIN, D = e % CIN;
        float s = 0.f;
        #pragma unroll 8
        for (int d = 0; d < HDIM; d++)
            s += sq[h * HDIM + d] * Wk[(size_t)D * CHID + h * HDIM + d];
        g_qWkT[e] = s;
    }
    if (tid < HEADS) {
        float s = 0.f;
        for (int d = 0; d < HDIM; d++)
            s += Wk_bias[tid * HDIM + d] * sq[tid * HDIM + d];
        g_biasq[tid] = s;
    }
    for (int e = tid; e < HEADS * 49; e += blockDim.x)
        g_rpeexp[e] = expf(rpe[e]);
}

// ---------------- SGEMM: C[b, m, hw] = A[m, :] . X[b, :, hw] + bias[m]
// A: [384, K] row-major; X: [B, K, 3136]; C: [B, 384, 3136]
// grid: (ceil(3136/128)=25, 384/128=3, 16); 256 threads, 8x8 per thread.
__global__ __launch_bounds__(256)
void sgemm_kernel(const float* __restrict__ A, const float* __restrict__ bias,
                  const float* __restrict__ X, float* __restrict__ C, int K) {
    const int b  = blockIdx.z;
    const int m0 = blockIdx.y * 128;
    const int n0 = blockIdx.x * 128;
    const float* Xb = X + (size_t)b * K * HW;
    float* Cb = C + (size_t)b * CHID * HW;

    __shared__ float As[8][128];
    __shared__ float Bs[8][128];

    const int tid = threadIdx.x;
    const int tx = tid & 15, ty = tid >> 4;
    float acc[8][8] = {};

    const int arow = tid >> 1;            // 0..127
    const int akc  = (tid & 1) * 4;       // 0 or 4
    const int bkr  = tid >> 5;            // 0..7
    const int bcol = (tid & 31) * 4;      // 0..124

    for (int k0 = 0; k0 < K; k0 += 8) {
        float4 av = *reinterpret_cast<const float4*>(
            &A[(size_t)(m0 + arow) * K + k0 + akc]);
        As[akc + 0][arow] = av.x;
        As[akc + 1][arow] = av.y;
        As[akc + 2][arow] = av.z;
        As[akc + 3][arow] = av.w;

        float4 bv = make_float4(0.f, 0.f, 0.f, 0.f);
        if (n0 + bcol < HW)
            bv = *reinterpret_cast<const float4*>(
                &Xb[(size_t)(k0 + bkr) * HW + n0 + bcol]);
        *reinterpret_cast<float4*>(&Bs[bkr][bcol]) = bv;
        __syncthreads();

        #pragma unroll
        for (int kk = 0; kk < 8; kk++) {
            float a[8], bb[8];
            #pragma unroll
            for (int i = 0; i < 8; i++) a[i] = As[kk][ty * 8 + i];
            #pragma unroll
            for (int j = 0; j < 8; j++) bb[j] = Bs[kk][tx * 8 + j];
            #pragma unroll
            for (int i = 0; i < 8; i++)
                #pragma unroll
                for (int j = 0; j < 8; j++)
                    acc[i][j] += a[i] * bb[j];
        }
        __syncthreads();
    }

    #pragma unroll
    for (int i = 0; i < 8; i++) {
        int m = m0 + ty * 8 + i;
        float bi = bias[m];
        #pragma unroll
        for (int j = 0; j < 8; j++) {
            int n = n0 + tx * 8 + j;
            if (n < HW) Cb[(size_t)m * HW + n] = acc[i][j] + bi;
        }
    }
}

// ---------------- cost kernel: COSTE[b,h,hw] = exp(qWkT[h,:].x[b,:,hw] + biasq[h])
__global__ __launch_bounds__(256)
void cost_kernel(const float* __restrict__ x) {
    __shared__ float4 sW4[HEADS * CIN / 4];   // [h][48] float4
    __shared__ float sb[HEADS];
    int tid = threadIdx.x;
    const float4* gW4 = reinterpret_cast<const float4*>(g_qWkT);
    for (int i = tid; i < HEADS * CIN / 4; i += 256) sW4[i] = gW4[i];
    if (tid < HEADS) sb[tid] = g_biasq[tid];
    __syncthreads();

    int idx = blockIdx.x * 256 + tid;
    if (idx >= BATCH * HW) return;
    int b = idx / HW, hw = idx % HW;
    const float* xb = x + (size_t)b * CIN * HW + hw;
    float acc[HEADS] = {};
    for (int D4 = 0; D4 < CIN / 4; D4++) {
        float x0 = xb[(size_t)(D4 * 4 + 0) * HW];
        float x1 = xb[(size_t)(D4 * 4 + 1) * HW];
        float x2 = xb[(size_t)(D4 * 4 + 2) * HW];
        float x3 = xb[(size_t)(D4 * 4 + 3) * HW];
        #pragma unroll
        for (int h = 0; h < HEADS; h++) {
            float4 w = sW4[h * (CIN / 4) + D4];
            acc[h] += x0 * w.x + x1 * w.y + x2 * w.z + x3 * w.w;
        }
    }
    float* cb = g_COSTE + (size_t)b * HEADS * HW + hw;
    #pragma unroll
    for (int h = 0; h < HEADS; h++)
        cb[(size_t)h * HW] = expf(acc[h] + sb[h]);
}

// ---------------- dwconv kernel: out_pre = conv(coste*V, w) / conv(coste, w)
// block = (b, head, channel-group of 12); 512 blocks, 256 threads
__global__ __launch_bounds__(256)
void dwconv_kernel() {
    const int bidx = blockIdx.x;
    const int cg = bidx & 3;
    const int head = (bidx >> 2) & 7;
    const int b = bidx >> 5;

    __shared__ float sc[62 * 64];   // padded cost_exp plane (pitch 64)
    __shared__ float sv[62 * 64];   // padded V channel plane
    __shared__ float sden[HW];
    __shared__ float w[49];

    const int tid = threadIdx.x;
    if (tid < 49) w[tid] = g_rpeexp[head * 49 + tid];

    const float* cp = g_COSTE + ((size_t)b * HEADS + head) * HW;
    for (int i = tid; i < 62 * 64; i += 256) {
        int r = i >> 6, c = i & 63;
        int y = r - 3, x = c - 3;
        float v = 0.f;
        if ((unsigned)y < 56u && (unsigned)x < 56u) v = cp[y * 56 + x];
        sc[i] = v;
    }
    __syncthreads();

    for (int p = tid; p < HW; p += 256) {
        int y = p / 56, x = p % 56;
        float s = 0.f;
        #pragma unroll
        for (int i = 0; i < 7; i++)
            #pragma unroll
            for (int j = 0; j < 7; j++)
                s += w[i * 7 + j] * sc[(y + i) * 64 + x + j];
        sden[p] = s;
    }

    for (int c = 0; c < 12; c++) {
        const int ch = head * HDIM + cg * 12 + c;
        const float* vp = g_V + ((size_t)b * CHID + ch) * HW;
        __syncthreads();
        for (int i = tid; i < 62 * 64; i += 256) {
            int r = i >> 6, cc = i & 63;
            int y = r - 3, x = cc - 3;
            float v = 0.f;
            if ((unsigned)y < 56u && (unsigned)x < 56u) v = vp[y * 56 + x];
            sv[i] = v;
        }
        __syncthreads();
        float* op = g_OUTPRE + ((size_t)b * CHID + ch) * HW;
        for (int p = tid; p < HW; p += 256) {
            int y = p / 56, x = p % 56;
            float s = 0.f;
            #pragma unroll
            for (int i = 0; i < 7; i++)
                #pragma unroll
                for (int j = 0; j < 7; j++) {
                    int o = (y + i) * 64 + x + j;
                    s += w[i * 7 + j] * sc[o] * sv[o];
                }
            op[p] = s / sden[p];
        }
    }
}

// ---------------- launch ----------------
extern "C" void kernel_launch(void* const* d_in, const int* in_sizes, int n_in,
                              void* d_out, int out_size) {
    const float* x        = (const float*)d_in[0];
    const float* query    = (const float*)d_in[1];
    const float* Wk       = (const float*)d_in[2];
    const float* Wk_bias  = (const float*)d_in[3];
    const float* to_v_w   = (const float*)d_in[4];
    const float* to_v_b   = (const float*)d_in[5];
    const float* to_out_w = (const float*)d_in[6];
    const float* to_out_b = (const float*)d_in[7];
    const float* rpe      = (const float*)d_in[8];

    // Cache symbol addresses on first (non-captured, correctness) call.
    static float* pV = nullptr;
    static float* pOUTPRE = nullptr;
    if (!pV) {
        cudaGetSymbolAddress((void**)&pV, g_V);
        cudaGetSymbolAddress((void**)&pOUTPRE, g_OUTPRE);
    }

    prep_kernel<<<1, 384>>>(query, Wk, Wk_bias, rpe);

    dim3 ggrid((HW + 127) / 128, CHID / 128, BATCH);  // (25, 3, 16)
    sgemm_kernel<<<ggrid, 256>>>(to_v_w, to_v_b, x, pV, CIN);

    cost_kernel<<<(BATCH * HW) / 256, 256>>>(x);

    dwconv_kernel<<<BATCH * HEADS * 4, 256>>>();

    sgemm_kernel<<<ggrid, 256>>>(to_out_w, to_out_b, pOUTPRE, (float*)d_out, CHID);
}

// round 2
// speedup vs baseline: 1.4472x; 1.4472x over previous
#include <cuda_runtime.h>
#include <math.h>

#define BATCH 16
#define CIN   192
#define CHID  384
#define HEADS 8
#define HDIM  48
#define IMG   56
#define HW    3136        // 56*56
#define KS    7

// ---------------- scratch (device globals; no allocs) ----------------
__device__ float g_qWkT[HEADS * CIN];        // [h][D]
__device__ float g_biasq[HEADS];
__device__ float g_rpeexp[HEADS * 49];
__device__ float g_V[(size_t)BATCH * CHID * HW];       // 77 MB
__device__ float g_COSTE[(size_t)BATCH * HEADS * HW];  // 1.6 MB
__device__ float g_OUTPRE[(size_t)BATCH * CHID * HW];  // 77 MB

// ---------------- K0: prep (q normalize, fold into Wk, exp rpe) ------
__global__ void prep_kernel(const float* __restrict__ query,
                            const float* __restrict__ Wk,
                            const float* __restrict__ Wk_bias,
                            const float* __restrict__ rpe) {
    __shared__ float sq[CHID];
    __shared__ float snorm[HEADS];
    int tid = threadIdx.x;
    float inv = 1.0f / (sqrtf((float)HDIM) + 1e-6f);
    if (tid < CHID) sq[tid] = query[tid] * inv;
    __syncthreads();
    if (tid < HEADS) {
        float s = 0.f;
        for (int d = 0; d < HDIM; d++) { float v = sq[tid * HDIM + d]; s += v * v; }
        snorm[tid] = sqrtf(s) + 1e-6f;
    }
    __syncthreads();
    if (tid < CHID) sq[tid] = sq[tid] / snorm[tid / HDIM];
    __syncthreads();
    for (int e = tid; e < HEADS * CIN; e += blockDim.x) {
        int h = e / CIN, D = e % CIN;
        float s = 0.f;
        #pragma unroll 8
        for (int d = 0; d < HDIM; d++)
            s += sq[h * HDIM + d] * Wk[(size_t)D * CHID + h * HDIM + d];
        g_qWkT[e] = s;
    }
    if (tid < HEADS) {
        float s = 0.f;
        for (int d = 0; d < HDIM; d++)
            s += Wk_bias[tid * HDIM + d] * sq[tid * HDIM + d];
        g_biasq[tid] = s;
    }
    for (int e = tid; e < HEADS * 49; e += blockDim.x)
        g_rpeexp[e] = expf(rpe[e]);
}

// ---------------- SGEMM: C[b, m, hw] = A[m, :] . X[b, :, hw] + bias[m]
// Double-buffered shared, BK=16, 8x8 microtile, 256 threads.
#define BM 128
#define BN 128
#define BK 16

__global__ __launch_bounds__(256, 2)
void sgemm_kernel(const float* __restrict__ A, const float* __restrict__ bias,
                  const float* __restrict__ X, float* __restrict__ C, int K) {
    const int b  = blockIdx.z;
    const int m0 = blockIdx.y * BM;
    const int n0 = blockIdx.x * BN;
    const float* Xb = X + (size_t)b * K * HW;
    float* Cb = C + (size_t)b * CHID * HW;

    __shared__ float As[2][BK][132];   // padded pitch to break STS conflicts
    __shared__ float Bs[2][BK][BN];

    const int tid = threadIdx.x;
    const int tx = tid & 15, ty = tid >> 4;

    // A tile: 128 rows x 16 k = 512 float4; thread loads f = tid, tid+256
    // B tile: 16 rows x 128 n = 512 float4
    float4 aReg[2], bReg[2];

    const int aRow0 = tid >> 2;             // f=tid      : row
    const int aKc0  = (tid & 3) * 4;
    const int aRow1 = (tid + 256) >> 2;
    const int aKc1  = ((tid + 256) & 3) * 4;
    const int bRow0 = tid >> 5;
    const int bCol0 = (tid & 31) * 4;
    const int bRow1 = (tid + 256) >> 5;
    const int bCol1 = ((tid + 256) & 31) * 4;
    const bool bOk0 = (n0 + bCol0) < HW;
    const bool bOk1 = (n0 + bCol1) < HW;

    float acc[8][8] = {};

    // prologue load tile 0
    aReg[0] = *reinterpret_cast<const float4*>(&A[(size_t)(m0 + aRow0) * K + aKc0]);
    aReg[1] = *reinterpret_cast<const float4*>(&A[(size_t)(m0 + aRow1) * K + aKc1]);
    bReg[0] = bOk0 ? *reinterpret_cast<const float4*>(&Xb[(size_t)bRow0 * HW + n0 + bCol0])
                   : make_float4(0, 0, 0, 0);
    bReg[1] = bOk1 ? *reinterpret_cast<const float4*>(&Xb[(size_t)bRow1 * HW + n0 + bCol1])
                   : make_float4(0, 0, 0, 0);
    {
        As[0][aKc0 + 0][aRow0] = aReg[0].x; As[0][aKc0 + 1][aRow0] = aReg[0].y;
        As[0][aKc0 + 2][aRow0] = aReg[0].z; As[0][aKc0 + 3][aRow0] = aReg[0].w;
        As[0][aKc1 + 0][aRow1] = aReg[1].x; As[0][aKc1 + 1][aRow1] = aReg[1].y;
        As[0][aKc1 + 2][aRow1] = aReg[1].z; As[0][aKc1 + 3][aRow1] = aReg[1].w;
        *reinterpret_cast<float4*>(&Bs[0][bRow0][bCol0]) = bReg[0];
        *reinterpret_cast<float4*>(&Bs[0][bRow1][bCol1]) = bReg[1];
    }
    __syncthreads();

    const int T = K / BK;
    for (int t = 0; t < T; t++) {
        const int buf = t & 1;
        if (t + 1 < T) {
            const int k0 = (t + 1) * BK;
            aReg[0] = *reinterpret_cast<const float4*>(&A[(size_t)(m0 + aRow0) * K + k0 + aKc0]);
            aReg[1] = *reinterpret_cast<const float4*>(&A[(size_t)(m0 + aRow1) * K + k0 + aKc1]);
            bReg[0] = bOk0 ? *reinterpret_cast<const float4*>(&Xb[(size_t)(k0 + bRow0) * HW + n0 + bCol0])
                           : make_float4(0, 0, 0, 0);
            bReg[1] = bOk1 ? *reinterpret_cast<const float4*>(&Xb[(size_t)(k0 + bRow1) * HW + n0 + bCol1])
                           : make_float4(0, 0, 0, 0);
        }
        #pragma unroll
        for (int kk = 0; kk < BK; kk++) {
            float a[8], bb[8];
            *reinterpret_cast<float4*>(a)      = *reinterpret_cast<const float4*>(&As[buf][kk][ty * 8]);
            *reinterpret_cast<float4*>(a + 4)  = *reinterpret_cast<const float4*>(&As[buf][kk][ty * 8 + 4]);
            *reinterpret_cast<float4*>(bb)     = *reinterpret_cast<const float4*>(&Bs[buf][kk][tx * 8]);
            *reinterpret_cast<float4*>(bb + 4) = *reinterpret_cast<const float4*>(&Bs[buf][kk][tx * 8 + 4]);
            #pragma unroll
            for (int i = 0; i < 8; i++)
                #pragma unroll
                for (int j = 0; j < 8; j++)
                    acc[i][j] += a[i] * bb[j];
        }
        if (t + 1 < T) {
            const int nb = 1 - buf;
            As[nb][aKc0 + 0][aRow0] = aReg[0].x; As[nb][aKc0 + 1][aRow0] = aReg[0].y;
            As[nb][aKc0 + 2][aRow0] = aReg[0].z; As[nb][aKc0 + 3][aRow0] = aReg[0].w;
            As[nb][aKc1 + 0][aRow1] = aReg[1].x; As[nb][aKc1 + 1][aRow1] = aReg[1].y;
            As[nb][aKc1 + 2][aRow1] = aReg[1].z; As[nb][aKc1 + 3][aRow1] = aReg[1].w;
            *reinterpret_cast<float4*>(&Bs[nb][bRow0][bCol0]) = bReg[0];
            *reinterpret_cast<float4*>(&Bs[nb][bRow1][bCol1]) = bReg[1];
        }
        __syncthreads();
    }

    #pragma unroll
    for (int i = 0; i < 8; i++) {
        int m = m0 + ty * 8 + i;
        float bi = bias[m];
        #pragma unroll
        for (int j4 = 0; j4 < 2; j4++) {
            int n = n0 + tx * 8 + j4 * 4;
            if (n < HW) {
                float4 o = make_float4(acc[i][j4 * 4 + 0] + bi, acc[i][j4 * 4 + 1] + bi,
                                       acc[i][j4 * 4 + 2] + bi, acc[i][j4 * 4 + 3] + bi);
                *reinterpret_cast<float4*>(&Cb[(size_t)m * HW + n]) = o;
            }
        }
    }
}

// ---------------- cost kernel: COSTE[b,h,hw] = exp(qWkT[h,:].x[b,:,hw] + biasq[h])
__global__ __launch_bounds__(256)
void cost_kernel(const float* __restrict__ x) {
    __shared__ float4 sW4[HEADS * CIN / 4];
    __shared__ float sb[HEADS];
    int tid = threadIdx.x;
    const float4* gW4 = reinterpret_cast<const float4*>(g_qWkT);
    for (int i = tid; i < HEADS * CIN / 4; i += 256) sW4[i] = gW4[i];
    if (tid < HEADS) sb[tid] = g_biasq[tid];
    __syncthreads();

    int idx = blockIdx.x * 256 + tid;
    if (idx >= BATCH * HW) return;
    int b = idx / HW, hw = idx % HW;
    const float* xb = x + (size_t)b * CIN * HW + hw;
    float acc[HEADS] = {};
    for (int D4 = 0; D4 < CIN / 4; D4++) {
        float x0 = xb[(size_t)(D4 * 4 + 0) * HW];
        float x1 = xb[(size_t)(D4 * 4 + 1) * HW];
        float x2 = xb[(size_t)(D4 * 4 + 2) * HW];
        float x3 = xb[(size_t)(D4 * 4 + 3) * HW];
        #pragma unroll
        for (int h = 0; h < HEADS; h++) {
            float4 w = sW4[h * (CIN / 4) + D4];
            acc[h] += x0 * w.x + x1 * w.y + x2 * w.z + x3 * w.w;
        }
    }
    float* cb = g_COSTE + (size_t)b * HEADS * HW + hw;
    #pragma unroll
    for (int h = 0; h < HEADS; h++)
        cb[(size_t)h * HW] = expf(acc[h] + sb[h]);
}

// ---------------- dwconv kernel ----------------
// block = (b, head, half of 24 channels); 256 blocks, 256 threads.
// weights in registers, c*v fused at load, 1x4 output microtile.
__global__ __launch_bounds__(256)
void dwconv_kernel() {
    const int bidx = blockIdx.x;
    const int half = bidx & 1;
    const int head = (bidx >> 1) & 7;
    const int b = bidx >> 4;

    __shared__ float sc[62 * 64];    // padded cost_exp plane (pitch 64)
    __shared__ float scv[62 * 64];   // padded cost_exp * V plane
    __shared__ float rden[HW];       // reciprocal denominator

    const int tid = threadIdx.x;

    float wr[49];
    #pragma unroll
    for (int i = 0; i < 49; i++) wr[i] = g_rpeexp[head * 49 + i];

    const float* cp = g_COSTE + ((size_t)b * HEADS + head) * HW;
    for (int i = tid; i < 62 * 64; i += 256) {
        int r = i >> 6, c = i & 63;
        int y = r - 3, x = c - 3;
        float v = 0.f;
        if ((unsigned)y < 56u && (unsigned)x < 56u) v = cp[y * 56 + x];
        sc[i] = v;
    }
    __syncthreads();

    // denominator (once per block)
    for (int it = tid; it < 784; it += 256) {
        int y = it / 14, x0 = (it % 14) * 4;
        float a0 = 0, a1 = 0, a2 = 0, a3 = 0;
        #pragma unroll
        for (int i = 0; i < 7; i++) {
            float r[10];
            #pragma unroll
            for (int j = 0; j < 10; j++) r[j] = sc[(y + i) * 64 + x0 + j];
            #pragma unroll
            for (int j = 0; j < 7; j++) {
                float wv = wr[i * 7 + j];
                a0 += wv * r[j]; a1 += wv * r[j + 1];
                a2 += wv * r[j + 2]; a3 += wv * r[j + 3];
            }
        }
        int p = y * 56 + x0;
        rden[p]     = 1.f / a0; rden[p + 1] = 1.f / a1;
        rden[p + 2] = 1.f / a2; rden[p + 3] = 1.f / a3;
    }

    for (int c = 0; c < 24; c++) {
        const int ch = head * HDIM + half * 24 + c;
        const float* vp = g_V + ((size_t)b * CHID + ch) * HW;
        __syncthreads();
        for (int i = tid; i < 62 * 64; i += 256) {
            int r = i >> 6, cc = i & 63;
            int y = r - 3, x = cc - 3;
            float v = 0.f;
            if ((unsigned)y < 56u && (unsigned)x < 56u) v = vp[y * 56 + x];
            scv[i] = sc[i] * v;
        }
        __syncthreads();
        float* op = g_OUTPRE + ((size_t)b * CHID + ch) * HW;
        for (int it = tid; it < 784; it += 256) {
            int y = it / 14, x0 = (it % 14) * 4;
            float a0 = 0, a1 = 0, a2 = 0, a3 = 0;
            #pragma unroll
            for (int i = 0; i < 7; i++) {
                float r[10];
                #pragma unroll
                for (int j = 0; j < 10; j++) r[j] = scv[(y + i) * 64 + x0 + j];
                #pragma unroll
                for (int j = 0; j < 7; j++) {
                    float wv = wr[i * 7 + j];
                    a0 += wv * r[j]; a1 += wv * r[j + 1];
                    a2 += wv * r[j + 2]; a3 += wv * r[j + 3];
                }
            }
            int p = y * 56 + x0;
            float4 o = make_float4(a0 * rden[p], a1 * rden[p + 1],
                                   a2 * rden[p + 2], a3 * rden[p + 3]);
            *reinterpret_cast<float4*>(&op[p]) = o;
        }
    }
}

// ---------------- launch ----------------
extern "C" void kernel_launch(void* const* d_in, const int* in_sizes, int n_in,
                              void* d_out, int out_size) {
    const float* x        = (const float*)d_in[0];
    const float* query    = (const float*)d_in[1];
    const float* Wk       = (const float*)d_in[2];
    const float* Wk_bias  = (const float*)d_in[3];
    const float* to_v_w   = (const float*)d_in[4];
    const float* to_v_b   = (const float*)d_in[5];
    const float* to_out_w = (const float*)d_in[6];
    const float* to_out_b = (const float*)d_in[7];
    const float* rpe      = (const float*)d_in[8];

    static float* pV = nullptr;
    static float* pOUTPRE = nullptr;
    if (!pV) {
        cudaGetSymbolAddress((void**)&pV, g_V);
        cudaGetSymbolAddress((void**)&pOUTPRE, g_OUTPRE);
    }

    prep_kernel<<<1, 384>>>(query, Wk, Wk_bias, rpe);

    dim3 ggrid((HW + BN - 1) / BN, CHID / BM, BATCH);  // (25, 3, 16)
    sgemm_kernel<<<ggrid, 256>>>(to_v_w, to_v_b, x, pV, CIN);

    cost_kernel<<<(BATCH * HW) / 256, 256>>>(x);

    dwconv_kernel<<<BATCH * HEADS * 2, 256>>>();

    sgemm_kernel<<<ggrid, 256>>>(to_out_w, to_out_b, pOUTPRE, (float*)d_out, CHID);
}

// round 3
// speedup vs baseline: 2.8540x; 1.9721x over previous
#include <cuda_runtime.h>
#include <math.h>
#include <stdint.h>

#define BATCH 16
#define CIN   192
#define CHID  384
#define HEADS 8
#define HDIM  48
#define IMG   56
#define HW    3136
#define KS    7

// ---------------- scratch ----------------
__device__ float g_qWkT[HEADS * CIN];
__device__ float g_biasq[HEADS];
__device__ float g_rpeexp[HEADS * 49];
__device__ float g_V[(size_t)BATCH * CHID * HW];
__device__ float g_COSTE[(size_t)BATCH * HEADS * HW];
__device__ float g_OUTPRE[(size_t)BATCH * CHID * HW];

__device__ __forceinline__ uint32_t f2tf32(float f) {
    uint32_t o;
    asm("cvt.rna.tf32.f32 %0, %1;" : "=r"(o) : "f"(f));
    return o;
}

// ---------------- K0: prep ----------------
__global__ void prep_kernel(const float* __restrict__ query,
                            const float* __restrict__ Wk,
                            const float* __restrict__ Wk_bias,
                            const float* __restrict__ rpe) {
    __shared__ float sq[CHID];
    __shared__ float snorm[HEADS];
    int tid = threadIdx.x;
    float inv = 1.0f / (sqrtf((float)HDIM) + 1e-6f);
    if (tid < CHID) sq[tid] = query[tid] * inv;
    __syncthreads();
    if (tid < HEADS) {
        float s = 0.f;
        for (int d = 0; d < HDIM; d++) { float v = sq[tid * HDIM + d]; s += v * v; }
        snorm[tid] = sqrtf(s) + 1e-6f;
    }
    __syncthreads();
    if (tid < CHID) sq[tid] = sq[tid] / snorm[tid / HDIM];
    __syncthreads();
    for (int e = tid; e < HEADS * CIN; e += blockDim.x) {
        int h = e / CIN, D = e % CIN;
        float s = 0.f;
        #pragma unroll 8
        for (int d = 0; d < HDIM; d++)
            s += sq[h * HDIM + d] * Wk[(size_t)D * CHID + h * HDIM + d];
        g_qWkT[e] = s;
    }
    if (tid < HEADS) {
        float s = 0.f;
        for (int d = 0; d < HDIM; d++)
            s += Wk_bias[tid * HDIM + d] * sq[tid * HDIM + d];
        g_biasq[tid] = s;
    }
    for (int e = tid; e < HEADS * 49; e += blockDim.x)
        g_rpeexp[e] = expf(rpe[e]);
}

// ---------------- TF32 tensor-core GEMM ----------------
// C[b, m, n] = A[m, :K] . X[b, :K, n] + bias[m]
// Tile: BM=128, BN=128, BK=16. 256 threads = 8 warps (4 m x 2 n),
// warp tile 32x64 -> 2x8 mma.m16n8k8 per k8 step.
#define BM 128
#define BN 128
#define BK 16
#define SPITCH 136   // 136 % 32 == 8 -> conflict-free frag loads

__global__ __launch_bounds__(256, 2)
void sgemm_tc_kernel(const float* __restrict__ A, const float* __restrict__ bias,
                     const float* __restrict__ X, float* __restrict__ C, int K) {
    const int b  = blockIdx.z;
    const int m0 = blockIdx.y * BM;
    const int n0 = blockIdx.x * BN;
    const float* Xb = X + (size_t)b * K * HW;
    float* Cb = C + (size_t)b * CHID * HW;

    __shared__ uint32_t As[2][BK][SPITCH];   // [k][m]
    __shared__ uint32_t Bs[2][BK][SPITCH];   // [k][n]

    const int tid  = threadIdx.x;
    const int warp = tid >> 5;
    const int lane = tid & 31;
    const int quad = lane >> 2;     // 0..7
    const int qi   = lane & 3;      // 0..3
    const int warpM = warp & 3;     // 0..3
    const int warpN = warp >> 2;    // 0..1
    const int m_base = warpM * 32;
    const int n_base = warpN * 64;

    // global load indices (same as fp32 version)
    const int aRow0 = tid >> 2;
    const int aKc0  = (tid & 3) * 4;
    const int aRow1 = (tid + 256) >> 2;
    const int aKc1  = ((tid + 256) & 3) * 4;
    const int bRow0 = tid >> 5;
    const int bCol0 = (tid & 31) * 4;
    const int bRow1 = (tid + 256) >> 5;
    const int bCol1 = ((tid + 256) & 31) * 4;
    const bool bOk0 = (n0 + bCol0) < HW;
    const bool bOk1 = (n0 + bCol1) < HW;

    float acc[2][8][4];
    #pragma unroll
    for (int i = 0; i < 2; i++)
        #pragma unroll
        for (int j = 0; j < 8; j++)
            #pragma unroll
            for (int r = 0; r < 4; r++) acc[i][j][r] = 0.f;

    float4 aReg[2], bReg[2];

    // prologue: tile 0
    aReg[0] = *reinterpret_cast<const float4*>(&A[(size_t)(m0 + aRow0) * K + aKc0]);
    aReg[1] = *reinterpret_cast<const float4*>(&A[(size_t)(m0 + aRow1) * K + aKc1]);
    bReg[0] = bOk0 ? *reinterpret_cast<const float4*>(&Xb[(size_t)bRow0 * HW + n0 + bCol0])
                   : make_float4(0, 0, 0, 0);
    bReg[1] = bOk1 ? *reinterpret_cast<const float4*>(&Xb[(size_t)bRow1 * HW + n0 + bCol1])
                   : make_float4(0, 0, 0, 0);
    {
        As[0][aKc0 + 0][aRow0] = f2tf32(aReg[0].x); As[0][aKc0 + 1][aRow0] = f2tf32(aReg[0].y);
        As[0][aKc0 + 2][aRow0] = f2tf32(aReg[0].z); As[0][aKc0 + 3][aRow0] = f2tf32(aReg[0].w);
        As[0][aKc1 + 0][aRow1] = f2tf32(aReg[1].x); As[0][aKc1 + 1][aRow1] = f2tf32(aReg[1].y);
        As[0][aKc1 + 2][aRow1] = f2tf32(aReg[1].z); As[0][aKc1 + 3][aRow1] = f2tf32(aReg[1].w);
        Bs[0][bRow0][bCol0 + 0] = f2tf32(bReg[0].x); Bs[0][bRow0][bCol0 + 1] = f2tf32(bReg[0].y);
        Bs[0][bRow0][bCol0 + 2] = f2tf32(bReg[0].z); Bs[0][bRow0][bCol0 + 3] = f2tf32(bReg[0].w);
        Bs[0][bRow1][bCol1 + 0] = f2tf32(bReg[1].x); Bs[0][bRow1][bCol1 + 1] = f2tf32(bReg[1].y);
        Bs[0][bRow1][bCol1 + 2] = f2tf32(bReg[1].z); Bs[0][bRow1][bCol1 + 3] = f2tf32(bReg[1].w);
    }
    __syncthreads();

    const int T = K / BK;
    for (int t = 0; t < T; t++) {
        const int buf = t & 1;
        if (t + 1 < T) {
            const int k0 = (t + 1) * BK;
            aReg[0] = *reinterpret_cast<const float4*>(&A[(size_t)(m0 + aRow0) * K + k0 + aKc0]);
            aReg[1] = *reinterpret_cast<const float4*>(&A[(size_t)(m0 + aRow1) * K + k0 + aKc1]);
            bReg[0] = bOk0 ? *reinterpret_cast<const float4*>(&Xb[(size_t)(k0 + bRow0) * HW + n0 + bCol0])
                           : make_float4(0, 0, 0, 0);
            bReg[1] = bOk1 ? *reinterpret_cast<const float4*>(&Xb[(size_t)(k0 + bRow1) * HW + n0 + bCol1])
                           : make_float4(0, 0, 0, 0);
        }

        #pragma unroll
        for (int kk = 0; kk < BK; kk += 8) {
            uint32_t af[2][4], bf[8][2];
            #pragma unroll
            for (int mt = 0; mt < 2; mt++) {
                const int mr = m_base + mt * 16 + quad;
                af[mt][0] = As[buf][kk + qi][mr];
                af[mt][1] = As[buf][kk + qi][mr + 8];
                af[mt][2] = As[buf][kk + qi + 4][mr];
                af[mt][3] = As[buf][kk + qi + 4][mr + 8];
            }
            #pragma unroll
            for (int nt = 0; nt < 8; nt++) {
                const int nc = n_base + nt * 8 + quad;
                bf[nt][0] = Bs[buf][kk + qi][nc];
                bf[nt][1] = Bs[buf][kk + qi + 4][nc];
            }
            #pragma unroll
            for (int mt = 0; mt < 2; mt++)
                #pragma unroll
                for (int nt = 0; nt < 8; nt++) {
                    asm volatile(
                        "mma.sync.aligned.m16n8k8.row.col.f32.tf32.tf32.f32 "
                        "{%0,%1,%2,%3}, {%4,%5,%6,%7}, {%8,%9}, {%0,%1,%2,%3};"
                        : "+f"(acc[mt][nt][0]), "+f"(acc[mt][nt][1]),
                          "+f"(acc[mt][nt][2]), "+f"(acc[mt][nt][3])
                        : "r"(af[mt][0]), "r"(af[mt][1]), "r"(af[mt][2]), "r"(af[mt][3]),
                          "r"(bf[nt][0]), "r"(bf[nt][1]));
                }
        }

        if (t + 1 < T) {
            const int nb = 1 - buf;
            As[nb][aKc0 + 0][aRow0] = f2tf32(aReg[0].x); As[nb][aKc0 + 1][aRow0] = f2tf32(aReg[0].y);
            As[nb][aKc0 + 2][aRow0] = f2tf32(aReg[0].z); As[nb][aKc0 + 3][aRow0] = f2tf32(aReg[0].w);
            As[nb][aKc1 + 0][aRow1] = f2tf32(aReg[1].x); As[nb][aKc1 + 1][aRow1] = f2tf32(aReg[1].y);
            As[nb][aKc1 + 2][aRow1] = f2tf32(aReg[1].z); As[nb][aKc1 + 3][aRow1] = f2tf32(aReg[1].w);
            Bs[nb][bRow0][bCol0 + 0] = f2tf32(bReg[0].x); Bs[nb][bRow0][bCol0 + 1] = f2tf32(bReg[0].y);
            Bs[nb][bRow0][bCol0 + 2] = f2tf32(bReg[0].z); Bs[nb][bRow0][bCol0 + 3] = f2tf32(bReg[0].w);
            Bs[nb][bRow1][bCol1 + 0] = f2tf32(bReg[1].x); Bs[nb][bRow1][bCol1 + 1] = f2tf32(bReg[1].y);
            Bs[nb][bRow1][bCol1 + 2] = f2tf32(bReg[1].z); Bs[nb][bRow1][bCol1 + 3] = f2tf32(bReg[1].w);
        }
        __syncthreads();
    }

    // epilogue
    #pragma unroll
    for (int mt = 0; mt < 2; mt++) {
        const int r = m0 + m_base + mt * 16 + quad;
        const float bi0 = bias[r];
        const float bi1 = bias[r + 8];
        #pragma unroll
        for (int nt = 0; nt < 8; nt++) {
            const int c = n0 + n_base + nt * 8 + qi * 2;
            if (c < HW) {
                float2 v0 = make_float2(acc[mt][nt][0] + bi0, acc[mt][nt][1] + bi0);
                float2 v1 = make_float2(acc[mt][nt][2] + bi1, acc[mt][nt][3] + bi1);
                *reinterpret_cast<float2*>(&Cb[(size_t)r * HW + c]) = v0;
                *reinterpret_cast<float2*>(&Cb[(size_t)(r + 8) * HW + c]) = v1;
            }
        }
    }
}

// ---------------- cost kernel ----------------
__global__ __launch_bounds__(256)
void cost_kernel(const float* __restrict__ x) {
    __shared__ float4 sW4[HEADS * CIN / 4];
    __shared__ float sb[HEADS];
    int tid = threadIdx.x;
    const float4* gW4 = reinterpret_cast<const float4*>(g_qWkT);
    for (int i = tid; i < HEADS * CIN / 4; i += 256) sW4[i] = gW4[i];
    if (tid < HEADS) sb[tid] = g_biasq[tid];
    __syncthreads();

    int idx = blockIdx.x * 256 + tid;
    if (idx >= BATCH * HW) return;
    int b = idx / HW, hw = idx % HW;
    const float* xb = x + (size_t)b * CIN * HW + hw;
    float acc[HEADS] = {};
    for (int D4 = 0; D4 < CIN / 4; D4++) {
        float x0 = xb[(size_t)(D4 * 4 + 0) * HW];
        float x1 = xb[(size_t)(D4 * 4 + 1) * HW];
        float x2 = xb[(size_t)(D4 * 4 + 2) * HW];
        float x3 = xb[(size_t)(D4 * 4 + 3) * HW];
        #pragma unroll
        for (int h = 0; h < HEADS; h++) {
            float4 w = sW4[h * (CIN / 4) + D4];
            acc[h] += x0 * w.x + x1 * w.y + x2 * w.z + x3 * w.w;
        }
    }
    float* cb = g_COSTE + (size_t)b * HEADS * HW + hw;
    #pragma unroll
    for (int h = 0; h < HEADS; h++)
        cb[(size_t)h * HW] = expf(acc[h] + sb[h]);
}

// ---------------- dwconv kernel ----------------
// block = (b, head, group of 12 channels); 512 blocks, 256 threads.
__global__ __launch_bounds__(256)
void dwconv_kernel() {
    const int bidx = blockIdx.x;
    const int cg = bidx & 3;
    const int head = (bidx >> 2) & 7;
    const int b = bidx >> 5;

    __shared__ float sc[62 * 64];
    __shared__ float scv[62 * 64];
    __shared__ float rden[HW];

    const int tid = threadIdx.x;

    float wr[49];
    #pragma unroll
    for (int i = 0; i < 49; i++) wr[i] = g_rpeexp[head * 49 + i];

    const float* cp = g_COSTE + ((size_t)b * HEADS + head) * HW;
    for (int i = tid; i < 62 * 64; i += 256) {
        int r = i >> 6, c = i & 63;
        int y = r - 3, x = c - 3;
        float v = 0.f;
        if ((unsigned)y < 56u && (unsigned)x < 56u) v = cp[y * 56 + x];
        sc[i] = v;
    }
    __syncthreads();

    for (int it = tid; it < 784; it += 256) {
        int y = it / 14, x0 = (it % 14) * 4;
        float a0 = 0, a1 = 0, a2 = 0, a3 = 0;
        #pragma unroll
        for (int i = 0; i < 7; i++) {
            float r[10];
            #pragma unroll
            for (int j = 0; j < 10; j++) r[j] = sc[(y + i) * 64 + x0 + j];
            #pragma unroll
            for (int j = 0; j < 7; j++) {
                float wv = wr[i * 7 + j];
                a0 += wv * r[j]; a1 += wv * r[j + 1];
                a2 += wv * r[j + 2]; a3 += wv * r[j + 3];
            }
        }
        int p = y * 56 + x0;
        rden[p]     = 1.f / a0; rden[p + 1] = 1.f / a1;
        rden[p + 2] = 1.f / a2; rden[p + 3] = 1.f / a3;
    }

    for (int c = 0; c < 12; c++) {
        const int ch = head * HDIM + cg * 12 + c;
        const float* vp = g_V + ((size_t)b * CHID + ch) * HW;
        __syncthreads();
        for (int i = tid; i < 62 * 64; i += 256) {
            int r = i >> 6, cc = i & 63;
            int y = r - 3, x = cc - 3;
            float v = 0.f;
            if ((unsigned)y < 56u && (unsigned)x < 56u) v = vp[y * 56 + x];
            scv[i] = sc[i] * v;
        }
        __syncthreads();
        float* op = g_OUTPRE + ((size_t)b * CHID + ch) * HW;
        for (int it = tid; it < 784; it += 256) {
            int y = it / 14, x0 = (it % 14) * 4;
            float a0 = 0, a1 = 0, a2 = 0, a3 = 0;
            #pragma unroll
            for (int i = 0; i < 7; i++) {
                float r[10];
                #pragma unroll
                for (int j = 0; j < 10; j++) r[j] = scv[(y + i) * 64 + x0 + j];
                #pragma unroll
                for (int j = 0; j < 7; j++) {
                    float wv = wr[i * 7 + j];
                    a0 += wv * r[j]; a1 += wv * r[j + 1];
                    a2 += wv * r[j + 2]; a3 += wv * r[j + 3];
                }
            }
            int p = y * 56 + x0;
            float4 o = make_float4(a0 * rden[p], a1 * rden[p + 1],
                                   a2 * rden[p + 2], a3 * rden[p + 3]);
            *reinterpret_cast<float4*>(&op[p]) = o;
        }
    }
}

// ---------------- launch ----------------
extern "C" void kernel_launch(void* const* d_in, const int* in_sizes, int n_in,
                              void* d_out, int out_size) {
    const float* x        = (const float*)d_in[0];
    const float* query    = (const float*)d_in[1];
    const float* Wk       = (const float*)d_in[2];
    const float* Wk_bias  = (const float*)d_in[3];
    const float* to_v_w   = (const float*)d_in[4];
    const float* to_v_b   = (const float*)d_in[5];
    const float* to_out_w = (const float*)d_in[6];
    const float* to_out_b = (const float*)d_in[7];
    const float* rpe      = (const float*)d_in[8];

    static float* pV = nullptr;
    static float* pOUTPRE = nullptr;
    if (!pV) {
        cudaGetSymbolAddress((void**)&pV, g_V);
        cudaGetSymbolAddress((void**)&pOUTPRE, g_OUTPRE);
    }

    prep_kernel<<<1, 384>>>(query, Wk, Wk_bias, rpe);

    dim3 ggrid((HW + BN - 1) / BN, CHID / BM, BATCH);  // (25, 3, 16)
    sgemm_tc_kernel<<<ggrid, 256>>>(to_v_w, to_v_b, x, pV, CIN);

    cost_kernel<<<(BATCH * HW) / 256, 256>>>(x);

    dwconv_kernel<<<BATCH * HEADS * 4, 256>>>();

    sgemm_tc_kernel<<<ggrid, 256>>>(to_out_w, to_out_b, pOUTPRE, (float*)d_out, CHID);
}

// round 4
// speedup vs baseline: 3.2286x; 1.1313x over previous
#include <cuda_runtime.h>
#include <math.h>
#include <stdint.h>

#define BATCH 16
#define CIN   192
#define CHID  384
#define HEADS 8
#define HDIM  48
#define IMG   56
#define HW    3136
#define KS    7

// ---------------- scratch ----------------
__device__ float g_qWkT[HEADS * CIN];
__device__ float g_biasq[HEADS];
__device__ float g_rpeexp[HEADS * 49];
__device__ float g_V[(size_t)BATCH * CHID * HW];
__device__ float g_COSTE[(size_t)BATCH * HEADS * HW];
__device__ float g_OUTPRE[(size_t)BATCH * CHID * HW];

__device__ __forceinline__ uint32_t f2tf32(float f) {
    uint32_t o;
    asm("cvt.rna.tf32.f32 %0, %1;" : "=r"(o) : "f"(f));
    return o;
}

// ---------------- K0: prep ----------------
__global__ void prep_kernel(const float* __restrict__ query,
                            const float* __restrict__ Wk,
                            const float* __restrict__ Wk_bias,
                            const float* __restrict__ rpe) {
    __shared__ float sq[CHID];
    __shared__ float snorm[HEADS];
    int tid = threadIdx.x;
    float inv = 1.0f / (sqrtf((float)HDIM) + 1e-6f);
    if (tid < CHID) sq[tid] = query[tid] * inv;
    __syncthreads();
    if (tid < HEADS) {
        float s = 0.f;
        for (int d = 0; d < HDIM; d++) { float v = sq[tid * HDIM + d]; s += v * v; }
        snorm[tid] = sqrtf(s) + 1e-6f;
    }
    __syncthreads();
    if (tid < CHID) sq[tid] = sq[tid] / snorm[tid / HDIM];
    __syncthreads();
    for (int e = tid; e < HEADS * CIN; e += blockDim.x) {
        int h = e / CIN, D = e % CIN;
        float s = 0.f;
        #pragma unroll 8
        for (int d = 0; d < HDIM; d++)
            s += sq[h * HDIM + d] * Wk[(size_t)D * CHID + h * HDIM + d];
        g_qWkT[e] = s;
    }
    if (tid < HEADS) {
        float s = 0.f;
        for (int d = 0; d < HDIM; d++)
            s += Wk_bias[tid * HDIM + d] * sq[tid * HDIM + d];
        g_biasq[tid] = s;
    }
    for (int e = tid; e < HEADS * 49; e += blockDim.x)
        g_rpeexp[e] = expf(rpe[e]);
}

// ---------------- TF32 tensor-core GEMM ----------------
#define BM 128
#define BN 128
#define BK 16
#define SPITCH 136

__global__ __launch_bounds__(256, 2)
void sgemm_tc_kernel(const float* __restrict__ A, const float* __restrict__ bias,
                     const float* __restrict__ X, float* __restrict__ C, int K) {
    const int b  = blockIdx.z;
    const int m0 = blockIdx.y * BM;
    const int n0 = blockIdx.x * BN;
    const float* Xb = X + (size_t)b * K * HW;
    float* Cb = C + (size_t)b * CHID * HW;

    __shared__ uint32_t As[2][BK][SPITCH];
    __shared__ uint32_t Bs[2][BK][SPITCH];

    const int tid  = threadIdx.x;
    const int warp = tid >> 5;
    const int lane = tid & 31;
    const int quad = lane >> 2;
    const int qi   = lane & 3;
    const int warpM = warp & 3;
    const int warpN = warp >> 2;
    const int m_base = warpM * 32;
    const int n_base = warpN * 64;

    const int aRow0 = tid >> 2;
    const int aKc0  = (tid & 3) * 4;
    const int aRow1 = (tid + 256) >> 2;
    const int aKc1  = ((tid + 256) & 3) * 4;
    const int bRow0 = tid >> 5;
    const int bCol0 = (tid & 31) * 4;
    const int bRow1 = (tid + 256) >> 5;
    const int bCol1 = ((tid + 256) & 31) * 4;
    const bool bOk0 = (n0 + bCol0) < HW;
    const bool bOk1 = (n0 + bCol1) < HW;

    float acc[2][8][4];
    #pragma unroll
    for (int i = 0; i < 2; i++)
        #pragma unroll
        for (int j = 0; j < 8; j++)
            #pragma unroll
            for (int r = 0; r < 4; r++) acc[i][j][r] = 0.f;

    float4 aReg[2], bReg[2];

    aReg[0] = *reinterpret_cast<const float4*>(&A[(size_t)(m0 + aRow0) * K + aKc0]);
    aReg[1] = *reinterpret_cast<const float4*>(&A[(size_t)(m0 + aRow1) * K + aKc1]);
    bReg[0] = bOk0 ? *reinterpret_cast<const float4*>(&Xb[(size_t)bRow0 * HW + n0 + bCol0])
                   : make_float4(0, 0, 0, 0);
    bReg[1] = bOk1 ? *reinterpret_cast<const float4*>(&Xb[(size_t)bRow1 * HW + n0 + bCol1])
                   : make_float4(0, 0, 0, 0);
    {
        As[0][aKc0 + 0][aRow0] = f2tf32(aReg[0].x); As[0][aKc0 + 1][aRow0] = f2tf32(aReg[0].y);
        As[0][aKc0 + 2][aRow0] = f2tf32(aReg[0].z); As[0][aKc0 + 3][aRow0] = f2tf32(aReg[0].w);
        As[0][aKc1 + 0][aRow1] = f2tf32(aReg[1].x); As[0][aKc1 + 1][aRow1] = f2tf32(aReg[1].y);
        As[0][aKc1 + 2][aRow1] = f2tf32(aReg[1].z); As[0][aKc1 + 3][aRow1] = f2tf32(aReg[1].w);
        Bs[0][bRow0][bCol0 + 0] = f2tf32(bReg[0].x); Bs[0][bRow0][bCol0 + 1] = f2tf32(bReg[0].y);
        Bs[0][bRow0][bCol0 + 2] = f2tf32(bReg[0].z); Bs[0][bRow0][bCol0 + 3] = f2tf32(bReg[0].w);
        Bs[0][bRow1][bCol1 + 0] = f2tf32(bReg[1].x); Bs[0][bRow1][bCol1 + 1] = f2tf32(bReg[1].y);
        Bs[0][bRow1][bCol1 + 2] = f2tf32(bReg[1].z); Bs[0][bRow1][bCol1 + 3] = f2tf32(bReg[1].w);
    }
    __syncthreads();

    const int T = K / BK;
    for (int t = 0; t < T; t++) {
        const int buf = t & 1;
        if (t + 1 < T) {
            const int k0 = (t + 1) * BK;
            aReg[0] = *reinterpret_cast<const float4*>(&A[(size_t)(m0 + aRow0) * K + k0 + aKc0]);
            aReg[1] = *reinterpret_cast<const float4*>(&A[(size_t)(m0 + aRow1) * K + k0 + aKc1]);
            bReg[0] = bOk0 ? *reinterpret_cast<const float4*>(&Xb[(size_t)(k0 + bRow0) * HW + n0 + bCol0])
                           : make_float4(0, 0, 0, 0);
            bReg[1] = bOk1 ? *reinterpret_cast<const float4*>(&Xb[(size_t)(k0 + bRow1) * HW + n0 + bCol1])
                           : make_float4(0, 0, 0, 0);
        }

        #pragma unroll
        for (int kk = 0; kk < BK; kk += 8) {
            uint32_t af[2][4], bf[8][2];
            #pragma unroll
            for (int mt = 0; mt < 2; mt++) {
                const int mr = m_base + mt * 16 + quad;
                af[mt][0] = As[buf][kk + qi][mr];
                af[mt][1] = As[buf][kk + qi][mr + 8];
                af[mt][2] = As[buf][kk + qi + 4][mr];
                af[mt][3] = As[buf][kk + qi + 4][mr + 8];
            }
            #pragma unroll
            for (int nt = 0; nt < 8; nt++) {
                const int nc = n_base + nt * 8 + quad;
                bf[nt][0] = Bs[buf][kk + qi][nc];
                bf[nt][1] = Bs[buf][kk + qi + 4][nc];
            }
            #pragma unroll
            for (int mt = 0; mt < 2; mt++)
                #pragma unroll
                for (int nt = 0; nt < 8; nt++) {
                    asm volatile(
                        "mma.sync.aligned.m16n8k8.row.col.f32.tf32.tf32.f32 "
                        "{%0,%1,%2,%3}, {%4,%5,%6,%7}, {%8,%9}, {%0,%1,%2,%3};"
                        : "+f"(acc[mt][nt][0]), "+f"(acc[mt][nt][1]),
                          "+f"(acc[mt][nt][2]), "+f"(acc[mt][nt][3])
                        : "r"(af[mt][0]), "r"(af[mt][1]), "r"(af[mt][2]), "r"(af[mt][3]),
                          "r"(bf[nt][0]), "r"(bf[nt][1]));
                }
        }

        if (t + 1 < T) {
            const int nb = 1 - buf;
            As[nb][aKc0 + 0][aRow0] = f2tf32(aReg[0].x); As[nb][aKc0 + 1][aRow0] = f2tf32(aReg[0].y);
            As[nb][aKc0 + 2][aRow0] = f2tf32(aReg[0].z); As[nb][aKc0 + 3][aRow0] = f2tf32(aReg[0].w);
            As[nb][aKc1 + 0][aRow1] = f2tf32(aReg[1].x); As[nb][aKc1 + 1][aRow1] = f2tf32(aReg[1].y);
            As[nb][aKc1 + 2][aRow1] = f2tf32(aReg[1].z); As[nb][aKc1 + 3][aRow1] = f2tf32(aReg[1].w);
            Bs[nb][bRow0][bCol0 + 0] = f2tf32(bReg[0].x); Bs[nb][bRow0][bCol0 + 1] = f2tf32(bReg[0].y);
            Bs[nb][bRow0][bCol0 + 2] = f2tf32(bReg[0].z); Bs[nb][bRow0][bCol0 + 3] = f2tf32(bReg[0].w);
            Bs[nb][bRow1][bCol1 + 0] = f2tf32(bReg[1].x); Bs[nb][bRow1][bCol1 + 1] = f2tf32(bReg[1].y);
            Bs[nb][bRow1][bCol1 + 2] = f2tf32(bReg[1].z); Bs[nb][bRow1][bCol1 + 3] = f2tf32(bReg[1].w);
        }
        __syncthreads();
    }

    #pragma unroll
    for (int mt = 0; mt < 2; mt++) {
        const int r = m0 + m_base + mt * 16 + quad;
        const float bi0 = bias[r];
        const float bi1 = bias[r + 8];
        #pragma unroll
        for (int nt = 0; nt < 8; nt++) {
            const int c = n0 + n_base + nt * 8 + qi * 2;
            if (c < HW) {
                float2 v0 = make_float2(acc[mt][nt][0] + bi0, acc[mt][nt][1] + bi0);
                float2 v1 = make_float2(acc[mt][nt][2] + bi1, acc[mt][nt][3] + bi1);
                *reinterpret_cast<float2*>(&Cb[(size_t)r * HW + c]) = v0;
                *reinterpret_cast<float2*>(&Cb[(size_t)(r + 8) * HW + c]) = v1;
            }
        }
    }
}

// ---------------- cost kernel ----------------
__global__ __launch_bounds__(256)
void cost_kernel(const float* __restrict__ x) {
    __shared__ float4 sW4[HEADS * CIN / 4];
    __shared__ float sb[HEADS];
    int tid = threadIdx.x;
    const float4* gW4 = reinterpret_cast<const float4*>(g_qWkT);
    for (int i = tid; i < HEADS * CIN / 4; i += 256) sW4[i] = gW4[i];
    if (tid < HEADS) sb[tid] = g_biasq[tid];
    __syncthreads();

    int idx = blockIdx.x * 256 + tid;
    if (idx >= BATCH * HW) return;
    int b = idx / HW, hw = idx % HW;
    const float* xb = x + (size_t)b * CIN * HW + hw;
    float acc[HEADS] = {};
    for (int D4 = 0; D4 < CIN / 4; D4++) {
        float x0 = xb[(size_t)(D4 * 4 + 0) * HW];
        float x1 = xb[(size_t)(D4 * 4 + 1) * HW];
        float x2 = xb[(size_t)(D4 * 4 + 2) * HW];
        float x3 = xb[(size_t)(D4 * 4 + 3) * HW];
        #pragma unroll
        for (int h = 0; h < HEADS; h++) {
            float4 w = sW4[h * (CIN / 4) + D4];
            acc[h] += x0 * w.x + x1 * w.y + x2 * w.z + x3 * w.w;
        }
    }
    float* cb = g_COSTE + (size_t)b * HEADS * HW + hw;
    #pragma unroll
    for (int h = 0; h < HEADS; h++)
        cb[(size_t)h * HW] = expf(acc[h] + sb[h]);
}

// ---------------- dwconv kernel v3 ----------------
// block = (b, head, group of 12 channels); 512 blocks, 256 threads.
// 4x4 output microtile: 10x10 register window serves 16 outputs.
// rden kept in registers (each thread divides only its own pixels).
// Smem pitch 68, interior at column offset 4 -> aligned float4 refills.
#define DP 68   // smem pitch (floats)

__global__ __launch_bounds__(256)
void dwconv_kernel() {
    const int bidx = blockIdx.x;
    const int cg = bidx & 3;
    const int head = (bidx >> 2) & 7;
    const int b = bidx >> 5;

    __shared__ __align__(16) float sc[62 * DP];
    __shared__ __align__(16) float scv[62 * DP];

    const int tid = threadIdx.x;

    float wr[49];
    #pragma unroll
    for (int i = 0; i < 49; i++) wr[i] = g_rpeexp[head * 49 + i];

    // fill cost plane (once) + zero scv halo (interior overwritten per channel)
    const float* cp = g_COSTE + ((size_t)b * HEADS + head) * HW;
    for (int i = tid; i < 62 * DP; i += 256) {
        int r = i / DP, c = i % DP;
        int y = r - 3, x = c - 4;
        float v = 0.f;
        if ((unsigned)y < 56u && (unsigned)x < 56u) v = cp[y * 56 + x];
        sc[i] = v;
        scv[i] = 0.f;
    }
    __syncthreads();

    const int y0 = (tid / 14) * 4;
    const int x0 = (tid % 14) * 4;
    const bool active = tid < 196;

    // denominator reciprocals -> registers
    float4 rden[4];
    if (active) {
        float acc[4][4] = {};
        #pragma unroll
        for (int i = 0; i < 10; i++) {
            float r[10];
            #pragma unroll
            for (int j = 0; j < 10; j++) r[j] = sc[(y0 + i) * DP + x0 + 1 + j];
            #pragma unroll
            for (int oy = 0; oy < 4; oy++) {
                const int wi = i - oy;
                if (wi >= 0 && wi < 7) {
                    #pragma unroll
                    for (int j = 0; j < 7; j++) {
                        float wv = wr[wi * 7 + j];
                        acc[oy][0] += wv * r[j];
                        acc[oy][1] += wv * r[j + 1];
                        acc[oy][2] += wv * r[j + 2];
                        acc[oy][3] += wv * r[j + 3];
                    }
                }
            }
        }
        #pragma unroll
        for (int oy = 0; oy < 4; oy++)
            rden[oy] = make_float4(1.f / acc[oy][0], 1.f / acc[oy][1],
                                   1.f / acc[oy][2], 1.f / acc[oy][3]);
    }

    for (int c = 0; c < 12; c++) {
        const int ch = head * HDIM + cg * 12 + c;
        const float* vp = g_V + ((size_t)b * CHID + ch) * HW;
        __syncthreads();
        // vectorized interior refill: scv = sc * V
        for (int i = tid; i < 784; i += 256) {
            int y = i / 14, c4 = (i % 14) * 4;
            float4 v = *reinterpret_cast<const float4*>(&vp[y * 56 + c4]);
            const float* sp = &sc[(y + 3) * DP + 4 + c4];
            float4 s = *reinterpret_cast<const float4*>(sp);
            float4 o = make_float4(v.x * s.x, v.y * s.y, v.z * s.z, v.w * s.w);
            *reinterpret_cast<float4*>(&scv[(y + 3) * DP + 4 + c4]) = o;
        }
        __syncthreads();
        if (active) {
            float acc[4][4] = {};
            #pragma unroll
            for (int i = 0; i < 10; i++) {
                float r[10];
                #pragma unroll
                for (int j = 0; j < 10; j++) r[j] = scv[(y0 + i) * DP + x0 + 1 + j];
                #pragma unroll
                for (int oy = 0; oy < 4; oy++) {
                    const int wi = i - oy;
                    if (wi >= 0 && wi < 7) {
                        #pragma unroll
                        for (int j = 0; j < 7; j++) {
                            float wv = wr[wi * 7 + j];
                            acc[oy][0] += wv * r[j];
                            acc[oy][1] += wv * r[j + 1];
                            acc[oy][2] += wv * r[j + 2];
                            acc[oy][3] += wv * r[j + 3];
                        }
                    }
                }
            }
            float* op = g_OUTPRE + ((size_t)b * CHID + ch) * HW;
            #pragma unroll
            for (int oy = 0; oy < 4; oy++) {
                float4 o = make_float4(acc[oy][0] * rden[oy].x, acc[oy][1] * rden[oy].y,
                                       acc[oy][2] * rden[oy].z, acc[oy][3] * rden[oy].w);
                *reinterpret_cast<float4*>(&op[(y0 + oy) * 56 + x0]) = o;
            }
        }
    }
}

// ---------------- launch ----------------
extern "C" void kernel_launch(void* const* d_in, const int* in_sizes, int n_in,
                              void* d_out, int out_size) {
    const float* x        = (const float*)d_in[0];
    const float* query    = (const float*)d_in[1];
    const float* Wk       = (const float*)d_in[2];
    const float* Wk_bias  = (const float*)d_in[3];
    const float* to_v_w   = (const float*)d_in[4];
    const float* to_v_b   = (const float*)d_in[5];
    const float* to_out_w = (const float*)d_in[6];
    const float* to_out_b = (const float*)d_in[7];
    const float* rpe      = (const float*)d_in[8];

    static float* pV = nullptr;
    static float* pOUTPRE = nullptr;
    if (!pV) {
        cudaGetSymbolAddress((void**)&pV, g_V);
        cudaGetSymbolAddress((void**)&pOUTPRE, g_OUTPRE);
    }

    prep_kernel<<<1, 384>>>(query, Wk, Wk_bias, rpe);

    dim3 ggrid((HW + BN - 1) / BN, CHID / BM, BATCH);  // (25, 3, 16)
    sgemm_tc_kernel<<<ggrid, 256>>>(to_v_w, to_v_b, x, pV, CIN);

    cost_kernel<<<(BATCH * HW) / 256, 256>>>(x);

    dwconv_kernel<<<BATCH * HEADS * 4, 256>>>();

    sgemm_tc_kernel<<<ggrid, 256>>>(to_out_w, to_out_b, pOUTPRE, (float*)d_out, CHID);
}

// round 5
// speedup vs baseline: 3.3362x; 1.0333x over previous
#include <cuda_runtime.h>
#include <math.h>
#include <stdint.h>

#define BATCH 16
#define CIN   192
#define CHID  384
#define HEADS 8
#define HDIM  48
#define IMG   56
#define HW    3136
#define KS    7

// ---------------- scratch ----------------
__device__ float g_qWkT[HEADS * CIN];
__device__ float g_biasq[HEADS];
__device__ float g_rpeexp[HEADS * 49];
__device__ float g_V[(size_t)BATCH * CHID * HW];
__device__ float g_COSTE[(size_t)BATCH * HEADS * HW];
__device__ float g_OUTPRE[(size_t)BATCH * CHID * HW];

__device__ __forceinline__ uint32_t f2tf32(float f) {
    uint32_t o;
    asm("cvt.rna.tf32.f32 %0, %1;" : "=r"(o) : "f"(f));
    return o;
}

__device__ __forceinline__ void cp_async16(uint32_t smem_dst, const void* gptr) {
    asm volatile("cp.async.cg.shared.global [%0], [%1], 16;" :: "r"(smem_dst), "l"(gptr));
}
__device__ __forceinline__ void cp_commit() {
    asm volatile("cp.async.commit_group;");
}
template <int N>
__device__ __forceinline__ void cp_wait() {
    asm volatile("cp.async.wait_group %0;" :: "n"(N));
}

// ---------------- K0: prep ----------------
__global__ void prep_kernel(const float* __restrict__ query,
                            const float* __restrict__ Wk,
                            const float* __restrict__ Wk_bias,
                            const float* __restrict__ rpe) {
    __shared__ float sq[CHID];
    __shared__ float snorm[HEADS];
    int tid = threadIdx.x;
    float inv = 1.0f / (sqrtf((float)HDIM) + 1e-6f);
    if (tid < CHID) sq[tid] = query[tid] * inv;
    __syncthreads();
    if (tid < HEADS) {
        float s = 0.f;
        for (int d = 0; d < HDIM; d++) { float v = sq[tid * HDIM + d]; s += v * v; }
        snorm[tid] = sqrtf(s) + 1e-6f;
    }
    __syncthreads();
    if (tid < CHID) sq[tid] = sq[tid] / snorm[tid / HDIM];
    __syncthreads();
    for (int e = tid; e < HEADS * CIN; e += blockDim.x) {
        int h = e / CIN, D = e % CIN;
        float s = 0.f;
        #pragma unroll 8
        for (int d = 0; d < HDIM; d++)
            s += sq[h * HDIM + d] * Wk[(size_t)D * CHID + h * HDIM + d];
        g_qWkT[e] = s;
    }
    if (tid < HEADS) {
        float s = 0.f;
        for (int d = 0; d < HDIM; d++)
            s += Wk_bias[tid * HDIM + d] * sq[tid * HDIM + d];
        g_biasq[tid] = s;
    }
    for (int e = tid; e < HEADS * 49; e += blockDim.x)
        g_rpeexp[e] = expf(rpe[e]);
}

// ---------------- TF32 tensor-core GEMM v2 ----------------
// C[b, m, n] = A[m, :K] . X[b, :K, n] + bias[m]
// 128 threads = 4 warps (2m x 2n), warp tile 64x64 -> 4x8 mma.m16n8k8 per k8.
// cp.async 2-stage pipeline; fp32 in smem, tf32 cvt at fragment load.
#define BM 128
#define BN 128
#define BK 16
#define APITCH 20    // floats; (20*quad+qi)%32 is a perfect bank permutation
#define BPITCH 136   // floats; 136%32==8 -> conflict-free

__global__ __launch_bounds__(128, 2)
void sgemm_tc_kernel(const float* __restrict__ A, const float* __restrict__ bias,
                     const float* __restrict__ X, float* __restrict__ C, int K) {
    const int b  = blockIdx.z;
    const int m0 = blockIdx.y * BM;
    const int n0 = blockIdx.x * BN;
    const float* Xb = X + (size_t)b * K * HW;
    float* Cb = C + (size_t)b * CHID * HW;

    __shared__ __align__(16) float sA[2][BM * APITCH];   // [m][k]
    __shared__ __align__(16) float sB[2][BK * BPITCH];   // [k][n]

    const int tid  = threadIdx.x;
    const int warp = tid >> 5;
    const int lane = tid & 31;
    const int quad = lane >> 2;
    const int qi   = lane & 3;
    const int m_base = (warp & 1) * 64;
    const int n_base = (warp >> 1) * 64;

    const uint32_t sA_u32 = (uint32_t)__cvta_generic_to_shared(&sA[0][0]);
    const uint32_t sB_u32 = (uint32_t)__cvta_generic_to_shared(&sB[0][0]);

    float acc[4][8][4];
    #pragma unroll
    for (int i = 0; i < 4; i++)
        #pragma unroll
        for (int j = 0; j < 8; j++)
            #pragma unroll
            for (int r = 0; r < 4; r++) acc[i][j][r] = 0.f;

    // cp.async load of one stage
    auto load_stage = [&](int buf, int k0) {
        // A: 128 rows x 16 floats = 512 x 16B chunks; 4 per thread
        #pragma unroll
        for (int p = 0; p < 4; p++) {
            int c = p * 128 + tid;
            int m = c >> 2, kc = (c & 3) * 4;
            cp_async16(sA_u32 + (buf * BM * APITCH + m * APITCH + kc) * 4,
                       &A[(size_t)(m0 + m) * K + k0 + kc]);
        }
        // B: 16 rows x 128 floats = 512 x 16B chunks; 4 per thread
        #pragma unroll
        for (int p = 0; p < 4; p++) {
            int c = p * 128 + tid;
            int kr = c >> 5, nc = (c & 31) * 4;
            int col = n0 + nc; if (col > HW - 4) col = HW - 4;   // clamp (garbage never stored)
            cp_async16(sB_u32 + (buf * BK * BPITCH + kr * BPITCH + nc) * 4,
                       &Xb[(size_t)(k0 + kr) * HW + col]);
        }
        cp_commit();
    };

    load_stage(0, 0);

    const int T = K / BK;
    for (int t = 0; t < T; t++) {
        const int buf = t & 1;
        if (t + 1 < T) { load_stage(1 - buf, (t + 1) * BK); cp_wait<1>(); }
        else           { cp_wait<0>(); }
        __syncthreads();

        const float* cA = &sA[buf][0];
        const float* cB = &sB[buf][0];
        #pragma unroll
        for (int kk = 0; kk < BK; kk += 8) {
            uint32_t af[4][4], bf[8][2];
            #pragma unroll
            for (int mt = 0; mt < 4; mt++) {
                const int mr = m_base + mt * 16 + quad;
                af[mt][0] = f2tf32(cA[mr * APITCH + kk + qi]);
                af[mt][1] = f2tf32(cA[(mr + 8) * APITCH + kk + qi]);
                af[mt][2] = f2tf32(cA[mr * APITCH + kk + qi + 4]);
                af[mt][3] = f2tf32(cA[(mr + 8) * APITCH + kk + qi + 4]);
            }
            #pragma unroll
            for (int nt = 0; nt < 8; nt++) {
                const int nc = n_base + nt * 8 + quad;
                bf[nt][0] = f2tf32(cB[(kk + qi) * BPITCH + nc]);
                bf[nt][1] = f2tf32(cB[(kk + qi + 4) * BPITCH + nc]);
            }
            #pragma unroll
            for (int mt = 0; mt < 4; mt++)
                #pragma unroll
                for (int nt = 0; nt < 8; nt++) {
                    asm volatile(
                        "mma.sync.aligned.m16n8k8.row.col.f32.tf32.tf32.f32 "
                        "{%0,%1,%2,%3}, {%4,%5,%6,%7}, {%8,%9}, {%0,%1,%2,%3};"
                        : "+f"(acc[mt][nt][0]), "+f"(acc[mt][nt][1]),
                          "+f"(acc[mt][nt][2]), "+f"(acc[mt][nt][3])
                        : "r"(af[mt][0]), "r"(af[mt][1]), "r"(af[mt][2]), "r"(af[mt][3]),
                          "r"(bf[nt][0]), "r"(bf[nt][1]));
                }
        }
        __syncthreads();
    }

    // epilogue
    #pragma unroll
    for (int mt = 0; mt < 4; mt++) {
        const int r = m0 + m_base + mt * 16 + quad;
        const float bi0 = bias[r];
        const float bi1 = bias[r + 8];
        #pragma unroll
        for (int nt = 0; nt < 8; nt++) {
            const int c = n0 + n_base + nt * 8 + qi * 2;
            if (c < HW) {
                float2 v0 = make_float2(acc[mt][nt][0] + bi0, acc[mt][nt][1] + bi0);
                float2 v1 = make_float2(acc[mt][nt][2] + bi1, acc[mt][nt][3] + bi1);
                *reinterpret_cast<float2*>(&Cb[(size_t)r * HW + c]) = v0;
                *reinterpret_cast<float2*>(&Cb[(size_t)(r + 8) * HW + c]) = v1;
            }
        }
    }
}

// ---------------- cost kernel ----------------
__global__ __launch_bounds__(256)
void cost_kernel(const float* __restrict__ x) {
    __shared__ float4 sW4[HEADS * CIN / 4];
    __shared__ float sb[HEADS];
    int tid = threadIdx.x;
    const float4* gW4 = reinterpret_cast<const float4*>(g_qWkT);
    for (int i = tid; i < HEADS * CIN / 4; i += 256) sW4[i] = gW4[i];
    if (tid < HEADS) sb[tid] = g_biasq[tid];
    __syncthreads();

    int idx = blockIdx.x * 256 + tid;
    if (idx >= BATCH * HW) return;
    int b = idx / HW, hw = idx % HW;
    const float* xb = x + (size_t)b * CIN * HW + hw;
    float acc[HEADS] = {};
    for (int D4 = 0; D4 < CIN / 4; D4++) {
        float x0 = xb[(size_t)(D4 * 4 + 0) * HW];
        float x1 = xb[(size_t)(D4 * 4 + 1) * HW];
        float x2 = xb[(size_t)(D4 * 4 + 2) * HW];
        float x3 = xb[(size_t)(D4 * 4 + 3) * HW];
        #pragma unroll
        for (int h = 0; h < HEADS; h++) {
            float4 w = sW4[h * (CIN / 4) + D4];
            acc[h] += x0 * w.x + x1 * w.y + x2 * w.z + x3 * w.w;
        }
    }
    float* cb = g_COSTE + (size_t)b * HEADS * HW + hw;
    #pragma unroll
    for (int h = 0; h < HEADS; h++)
        cb[(size_t)h * HW] = expf(acc[h] + sb[h]);
}

// ---------------- dwconv kernel ----------------
#define DP 68

__global__ __launch_bounds__(256)
void dwconv_kernel() {
    const int bidx = blockIdx.x;
    const int cg = bidx & 3;
    const int head = (bidx >> 2) & 7;
    const int b = bidx >> 5;

    __shared__ __align__(16) float sc[62 * DP];
    __shared__ __align__(16) float scv[62 * DP];

    const int tid = threadIdx.x;

    float wr[49];
    #pragma unroll
    for (int i = 0; i < 49; i++) wr[i] = g_rpeexp[head * 49 + i];

    const float* cp = g_COSTE + ((size_t)b * HEADS + head) * HW;
    for (int i = tid; i < 62 * DP; i += 256) {
        int r = i / DP, c = i % DP;
        int y = r - 3, x = c - 4;
        float v = 0.f;
        if ((unsigned)y < 56u && (unsigned)x < 56u) v = cp[y * 56 + x];
        sc[i] = v;
        scv[i] = 0.f;
    }
    __syncthreads();

    const int y0 = (tid / 14) * 4;
    const int x0 = (tid % 14) * 4;
    const bool active = tid < 196;

    float4 rden[4];
    if (active) {
        float acc[4][4] = {};
        #pragma unroll
        for (int i = 0; i < 10; i++) {
            float r[10];
            #pragma unroll
            for (int j = 0; j < 10; j++) r[j] = sc[(y0 + i) * DP + x0 + 1 + j];
            #pragma unroll
            for (int oy = 0; oy < 4; oy++) {
                const int wi = i - oy;
                if (wi >= 0 && wi < 7) {
                    #pragma unroll
                    for (int j = 0; j < 7; j++) {
                        float wv = wr[wi * 7 + j];
                        acc[oy][0] += wv * r[j];
                        acc[oy][1] += wv * r[j + 1];
                        acc[oy][2] += wv * r[j + 2];
                        acc[oy][3] += wv * r[j + 3];
                    }
                }
            }
        }
        #pragma unroll
        for (int oy = 0; oy < 4; oy++)
            rden[oy] = make_float4(1.f / acc[oy][0], 1.f / acc[oy][1],
                                   1.f / acc[oy][2], 1.f / acc[oy][3]);
    }

    for (int c = 0; c < 12; c++) {
        const int ch = head * HDIM + cg * 12 + c;
        const float* vp = g_V + ((size_t)b * CHID + ch) * HW;
        __syncthreads();
        for (int i = tid; i < 784; i += 256) {
            int y = i / 14, c4 = (i % 14) * 4;
            float4 v = *reinterpret_cast<const float4*>(&vp[y * 56 + c4]);
            float4 s = *reinterpret_cast<const float4*>(&sc[(y + 3) * DP + 4 + c4]);
            float4 o = make_float4(v.x * s.x, v.y * s.y, v.z * s.z, v.w * s.w);
            *reinterpret_cast<float4*>(&scv[(y + 3) * DP + 4 + c4]) = o;
        }
        __syncthreads();
        if (active) {
            float acc[4][4] = {};
            #pragma unroll
            for (int i = 0; i < 10; i++) {
                float r[10];
                #pragma unroll
                for (int j = 0; j < 10; j++) r[j] = scv[(y0 + i) * DP + x0 + 1 + j];
                #pragma unroll
                for (int oy = 0; oy < 4; oy++) {
                    const int wi = i - oy;
                    if (wi >= 0 && wi < 7) {
                        #pragma unroll
                        for (int j = 0; j < 7; j++) {
                            float wv = wr[wi * 7 + j];
                            acc[oy][0] += wv * r[j];
                            acc[oy][1] += wv * r[j + 1];
                            acc[oy][2] += wv * r[j + 2];
                            acc[oy][3] += wv * r[j + 3];
                        }
                    }
                }
            }
            float* op = g_OUTPRE + ((size_t)b * CHID + ch) * HW;
            #pragma unroll
            for (int oy = 0; oy < 4; oy++) {
                float4 o = make_float4(acc[oy][0] * rden[oy].x, acc[oy][1] * rden[oy].y,
                                       acc[oy][2] * rden[oy].z, acc[oy][3] * rden[oy].w);
                *reinterpret_cast<float4*>(&op[(y0 + oy) * 56 + x0]) = o;
            }
        }
    }
}

// ---------------- launch ----------------
extern "C" void kernel_launch(void* const* d_in, const int* in_sizes, int n_in,
                              void* d_out, int out_size) {
    const float* x        = (const float*)d_in[0];
    const float* query    = (const float*)d_in[1];
    const float* Wk       = (const float*)d_in[2];
    const float* Wk_bias  = (const float*)d_in[3];
    const float* to_v_w   = (const float*)d_in[4];
    const float* to_v_b   = (const float*)d_in[5];
    const float* to_out_w = (const float*)d_in[6];
    const float* to_out_b = (const float*)d_in[7];
    const float* rpe      = (const float*)d_in[8];

    static float* pV = nullptr;
    static float* pOUTPRE = nullptr;
    if (!pV) {
        cudaGetSymbolAddress((void**)&pV, g_V);
        cudaGetSymbolAddress((void**)&pOUTPRE, g_OUTPRE);
    }

    prep_kernel<<<1, 384>>>(query, Wk, Wk_bias, rpe);

    dim3 ggrid((HW + BN - 1) / BN, CHID / BM, BATCH);  // (25, 3, 16)
    sgemm_tc_kernel<<<ggrid, 128>>>(to_v_w, to_v_b, x, pV, CIN);

    cost_kernel<<<(BATCH * HW) / 256, 256>>>(x);

    dwconv_kernel<<<BATCH * HEADS * 4, 256>>>();

    sgemm_tc_kernel<<<ggrid, 128>>>(to_out_w, to_out_b, pOUTPRE, (float*)d_out, CHID);
}

// round 8
// speedup vs baseline: 3.8918x; 1.1665x over previous
#include <cuda_runtime.h>
#include <cuda_fp16.h>
#include <math.h>
#include <stdint.h>

#define BATCH 16
#define CIN   192
#define CHID  384
#define HEADS 8
#define HDIM  48
#define IMG   56
#define HW    3136
#define KS    7

// ---------------- scratch ----------------
__device__ float g_qWkT[HEADS * CIN];
__device__ float g_biasq[HEADS];
__device__ float g_rpeexp[HEADS * 49];
__device__ float g_V[(size_t)BATCH * CHID * HW];
__device__ float g_COSTE[(size_t)BATCH * HEADS * HW];
__device__ float g_OUTPRE[(size_t)BATCH * CHID * HW];

__device__ __forceinline__ uint32_t smem_u32(const void* p) {
    uint32_t a;
    asm("{ .reg .u64 t; cvta.to.shared.u64 t, %1; cvt.u32.u64 %0, t; }" : "=r"(a) : "l"(p));
    return a;
}
__device__ __forceinline__ uint32_t packh2(float x, float y) {
    __half2 h = __floats2half2_rn(x, y);
    return *reinterpret_cast<uint32_t*>(&h);
}

// ---------------- K0: prep ----------------
__global__ void prep_kernel(const float* __restrict__ query,
                            const float* __restrict__ Wk,
                            const float* __restrict__ Wk_bias,
                            const float* __restrict__ rpe) {
    __shared__ float sq[CHID];
    __shared__ float snorm[HEADS];
    int tid = threadIdx.x;
    float inv = 1.0f / (sqrtf((float)HDIM) + 1e-6f);
    if (tid < CHID) sq[tid] = query[tid] * inv;
    __syncthreads();
    if (tid < HEADS) {
        float s = 0.f;
        for (int d = 0; d < HDIM; d++) { float v = sq[tid * HDIM + d]; s += v * v; }
        snorm[tid] = sqrtf(s) + 1e-6f;
    }
    __syncthreads();
    if (tid < CHID) sq[tid] = sq[tid] / snorm[tid / HDIM];
    __syncthreads();
    for (int e = tid; e < HEADS * CIN; e += blockDim.x) {
        int h = e / CIN, D = e % CIN;
        float s = 0.f;
        #pragma unroll 8
        for (int d = 0; d < HDIM; d++)
            s += sq[h * HDIM + d] * Wk[(size_t)D * CHID + h * HDIM + d];
        g_qWkT[e] = s;
    }
    if (tid < HEADS) {
        float s = 0.f;
        for (int d = 0; d < HDIM; d++)
            s += Wk_bias[tid * HDIM + d] * sq[tid * HDIM + d];
        g_biasq[tid] = s;
    }
    for (int e = tid; e < HEADS * 49; e += blockDim.x)
        g_rpeexp[e] = expf(rpe[e]);
}

// ---------------- FP16 tensor-core GEMM (m16n8k16 + ldmatrix) ----------------
// C[b, m, n] = A[m, :K] . X[b, :K, n] + bias[m]
// 128 threads = 4 warps (2m x 2n), warp tile 64x64.
// A smem: [m][k16] fp16, row pitch 48B (conflict-free ldmatrix).
// B smem: [k16][n128] fp16, row pitch 272B (conflict-free ldmatrix.trans).
#define BM 128
#define BN 128
#define BK 16
#define APB 48    // A row pitch bytes
#define BPB 272   // B row pitch bytes
#define ASTG (BM * APB)   // 6144
#define BSTG (BK * BPB)   // 4352

__global__ __launch_bounds__(128, 2)
void sgemm_fp16(const float* __restrict__ A, const float* __restrict__ bias,
                const float* __restrict__ X, float* __restrict__ C, int K) {
    const int b  = blockIdx.z;
    const int m0 = blockIdx.y * BM;
    const int n0 = blockIdx.x * BN;
    const float* Xb = X + (size_t)b * K * HW;
    float* Cb = C + (size_t)b * CHID * HW;

    __shared__ __align__(16) char sA[2][ASTG];
    __shared__ __align__(16) char sB[2][BSTG];

    const int tid  = threadIdx.x;
    const int warp = tid >> 5;
    const int lane = tid & 31;
    const int quad = lane >> 2;
    const int qi   = lane & 3;
    const int m_base = (warp & 1) * 64;
    const int n_base = (warp >> 1) * 64;

    const uint32_t uA = smem_u32(&sA[0][0]);
    const uint32_t uB = smem_u32(&sB[0][0]);

    // ldmatrix lane addresses (fixed per thread, per stage add buf offset)
    // A: row = m_base + mt*16 + (lane&15); kcol halves by lane>>4
    const uint32_t aAddrBase = uA + (uint32_t)(m_base + (lane & 15)) * APB + (uint32_t)((lane >> 4) * 8) * 2;
    // B: krow = lane&15 ; ncol = n_base + nt*16 + (lane>>4)*8
    const uint32_t bAddrBase = uB + (uint32_t)(lane & 15) * BPB + (uint32_t)(n_base + (lane >> 4) * 8) * 2;

    float acc[4][8][4];
    #pragma unroll
    for (int i = 0; i < 4; i++)
        #pragma unroll
        for (int j = 0; j < 8; j++)
            #pragma unroll
            for (int r = 0; r < 4; r++) acc[i][j][r] = 0.f;

    // global staging indices: A tile 128x16 fp32 = 512 float4; B tile 16x128 = 512 float4
    const int aM  = tid >> 1;              // wrong for 4-per-thread; use generic below
    (void)aM;
    float4 aR[4], bR[4];

    auto load_regs = [&](int k0) {
        #pragma unroll
        for (int p = 0; p < 4; p++) {
            int c = p * 128 + tid;
            int m = c >> 2, kc = (c & 3) * 4;
            aR[p] = *reinterpret_cast<const float4*>(&A[(size_t)(m0 + m) * K + k0 + kc]);
        }
        #pragma unroll
        for (int p = 0; p < 4; p++) {
            int c = p * 128 + tid;
            int kr = c >> 5, nc = (c & 31) * 4;
            int col = n0 + nc; if (col > HW - 4) col = HW - 4;
            bR[p] = *reinterpret_cast<const float4*>(&Xb[(size_t)(k0 + kr) * HW + col]);
        }
    };
    auto store_stage = [&](int buf) {
        #pragma unroll
        for (int p = 0; p < 4; p++) {
            int c = p * 128 + tid;
            int m = c >> 2, kc = (c & 3) * 4;
            uint2 v = make_uint2(packh2(aR[p].x, aR[p].y), packh2(aR[p].z, aR[p].w));
            *reinterpret_cast<uint2*>(&sA[buf][m * APB + kc * 2]) = v;
        }
        #pragma unroll
        for (int p = 0; p < 4; p++) {
            int c = p * 128 + tid;
            int kr = c >> 5, nc = (c & 31) * 4;
            uint2 v = make_uint2(packh2(bR[p].x, bR[p].y), packh2(bR[p].z, bR[p].w));
            *reinterpret_cast<uint2*>(&sB[buf][kr * BPB + nc * 2]) = v;
        }
    };

    load_regs(0);
    store_stage(0);
    __syncthreads();

    const int T = K / BK;
    for (int t = 0; t < T; t++) {
        const int buf = t & 1;
        if (t + 1 < T) load_regs((t + 1) * BK);

        uint32_t af[4][4], bf[4][4];
        const uint32_t aOff = aAddrBase + (buf ? ASTG : 0);
        const uint32_t bOff = bAddrBase + (buf ? BSTG : 0);
        #pragma unroll
        for (int mt = 0; mt < 4; mt++) {
            asm volatile("ldmatrix.sync.aligned.m8n8.x4.shared.b16 {%0,%1,%2,%3}, [%4];"
                : "=r"(af[mt][0]), "=r"(af[mt][1]), "=r"(af[mt][2]), "=r"(af[mt][3])
                : "r"(aOff + (uint32_t)(mt * 16) * APB));
        }
        #pragma unroll
        for (int j = 0; j < 4; j++) {
            asm volatile("ldmatrix.sync.aligned.m8n8.x4.trans.shared.b16 {%0,%1,%2,%3}, [%4];"
                : "=r"(bf[j][0]), "=r"(bf[j][1]), "=r"(bf[j][2]), "=r"(bf[j][3])
                : "r"(bOff + (uint32_t)(j * 16) * 2));
        }
        #pragma unroll
        for (int mt = 0; mt < 4; mt++)
            #pragma unroll
            for (int nt = 0; nt < 8; nt++) {
                const int j = nt >> 1, h = (nt & 1) * 2;
                asm volatile(
                    "mma.sync.aligned.m16n8k16.row.col.f32.f16.f16.f32 "
                    "{%0,%1,%2,%3}, {%4,%5,%6,%7}, {%8,%9}, {%0,%1,%2,%3};"
                    : "+f"(acc[mt][nt][0]), "+f"(acc[mt][nt][1]),
                      "+f"(acc[mt][nt][2]), "+f"(acc[mt][nt][3])
                    : "r"(af[mt][0]), "r"(af[mt][1]), "r"(af[mt][2]), "r"(af[mt][3]),
                      "r"(bf[j][h]), "r"(bf[j][h + 1]));
            }

        if (t + 1 < T) {
            __syncthreads();           // everyone done reading buf before overwrite of other? (other buf is free)
            store_stage(1 - buf);
        }
        __syncthreads();
    }

    // epilogue
    #pragma unroll
    for (int mt = 0; mt < 4; mt++) {
        const int r = m0 + m_base + mt * 16 + quad;
        const float bi0 = bias[r];
        const float bi1 = bias[r + 8];
        #pragma unroll
        for (int nt = 0; nt < 8; nt++) {
            const int c = n0 + n_base + nt * 8 + qi * 2;
            if (c < HW) {
                float2 v0 = make_float2(acc[mt][nt][0] + bi0, acc[mt][nt][1] + bi0);
                float2 v1 = make_float2(acc[mt][nt][2] + bi1, acc[mt][nt][3] + bi1);
                *reinterpret_cast<float2*>(&Cb[(size_t)r * HW + c]) = v0;
                *reinterpret_cast<float2*>(&Cb[(size_t)(r + 8) * HW + c]) = v1;
            }
        }
    }
}

// ---------------- cost kernel ----------------
__global__ __launch_bounds__(256)
void cost_kernel(const float* __restrict__ x) {
    __shared__ float4 sW4[HEADS * CIN / 4];
    __shared__ float sb[HEADS];
    int tid = threadIdx.x;
    const float4* gW4 = reinterpret_cast<const float4*>(g_qWkT);
    for (int i = tid; i < HEADS * CIN / 4; i += 256) sW4[i] = gW4[i];
    if (tid < HEADS) sb[tid] = g_biasq[tid];
    __syncthreads();

    int idx = blockIdx.x * 256 + tid;
    if (idx >= BATCH * HW) return;
    int b = idx / HW, hw = idx % HW;
    const float* xb = x + (size_t)b * CIN * HW + hw;
    float acc[HEADS] = {};
    for (int D4 = 0; D4 < CIN / 4; D4++) {
        float x0 = xb[(size_t)(D4 * 4 + 0) * HW];
        float x1 = xb[(size_t)(D4 * 4 + 1) * HW];
        float x2 = xb[(size_t)(D4 * 4 + 2) * HW];
        float x3 = xb[(size_t)(D4 * 4 + 3) * HW];
        #pragma unroll
        for (int h = 0; h < HEADS; h++) {
            float4 w = sW4[h * (CIN / 4) + D4];
            acc[h] += x0 * w.x + x1 * w.y + x2 * w.z + x3 * w.w;
        }
    }
    float* cb = g_COSTE + (size_t)b * HEADS * HW + hw;
    #pragma unroll
    for (int h = 0; h < HEADS; h++)
        cb[(size_t)h * HW] = expf(acc[h] + sb[h]);
}

// ---------------- dwconv kernel ----------------
#define DP 68

__global__ __launch_bounds__(256)
void dwconv_kernel() {
    const int bidx = blockIdx.x;
    const int cg = bidx & 3;
    const int head = (bidx >> 2) & 7;
    const int b = bidx >> 5;

    __shared__ __align__(16) float sc[62 * DP];
    __shared__ __align__(16) float scv[62 * DP];

    const int tid = threadIdx.x;

    float wr[49];
    #pragma unroll
    for (int i = 0; i < 49; i++) wr[i] = g_rpeexp[head * 49 + i];

    const float* cp = g_COSTE + ((size_t)b * HEADS + head) * HW;
    for (int i = tid; i < 62 * DP; i += 256) {
        int r = i / DP, c = i % DP;
        int y = r - 3, x = c - 4;
        float v = 0.f;
        if ((unsigned)y < 56u && (unsigned)x < 56u) v = cp[y * 56 + x];
        sc[i] = v;
        scv[i] = 0.f;
    }
    __syncthreads();

    const int y0 = (tid / 14) * 4;
    const int x0 = (tid % 14) * 4;
    const bool active = tid < 196;

    float4 rden[4];
    if (active) {
        float acc[4][4] = {};
        #pragma unroll
        for (int i = 0; i < 10; i++) {
            float r[10];
            #pragma unroll
            for (int j = 0; j < 10; j++) r[j] = sc[(y0 + i) * DP + x0 + 1 + j];
            #pragma unroll
            for (int oy = 0; oy < 4; oy++) {
                const int wi = i - oy;
                if (wi >= 0 && wi < 7) {
                    #pragma unroll
                    for (int j = 0; j < 7; j++) {
                        float wv = wr[wi * 7 + j];
                        acc[oy][0] += wv * r[j];
                        acc[oy][1] += wv * r[j + 1];
                        acc[oy][2] += wv * r[j + 2];
                        acc[oy][3] += wv * r[j + 3];
                    }
                }
            }
        }
        #pragma unroll
        for (int oy = 0; oy < 4; oy++)
            rden[oy] = make_float4(1.f / acc[oy][0], 1.f / acc[oy][1],
                                   1.f / acc[oy][2], 1.f / acc[oy][3]);
    }

    for (int c = 0; c < 12; c++) {
        const int ch = head * HDIM + cg * 12 + c;
        const float* vp = g_V + ((size_t)b * CHID + ch) * HW;
        __syncthreads();
        for (int i = tid; i < 784; i += 256) {
            int y = i / 14, c4 = (i % 14) * 4;
            float4 v = *reinterpret_cast<const float4*>(&vp[y * 56 + c4]);
            float4 s = *reinterpret_cast<const float4*>(&sc[(y + 3) * DP + 4 + c4]);
            float4 o = make_float4(v.x * s.x, v.y * s.y, v.z * s.z, v.w * s.w);
            *reinterpret_cast<float4*>(&scv[(y + 3) * DP + 4 + c4]) = o;
        }
        __syncthreads();
        if (active) {
            float acc[4][4] = {};
            #pragma unroll
            for (int i = 0; i < 10; i++) {
                float r[10];
                #pragma unroll
                for (int j = 0; j < 10; j++) r[j] = scv[(y0 + i) * DP + x0 + 1 + j];
                #pragma unroll
                for (int oy = 0; oy < 4; oy++) {
                    const int wi = i - oy;
                    if (wi >= 0 && wi < 7) {
                        #pragma unroll
                        for (int j = 0; j < 7; j++) {
                            float wv = wr[wi * 7 + j];
                            acc[oy][0] += wv * r[j];
                            acc[oy][1] += wv * r[j + 1];
                            acc[oy][2] += wv * r[j + 2];
                            acc[oy][3] += wv * r[j + 3];
                        }
                    }
                }
            }
            float* op = g_OUTPRE + ((size_t)b * CHID + ch) * HW;
            #pragma unroll
            for (int oy = 0; oy < 4; oy++) {
                float4 o = make_float4(acc[oy][0] * rden[oy].x, acc[oy][1] * rden[oy].y,
                                       acc[oy][2] * rden[oy].z, acc[oy][3] * rden[oy].w);
                *reinterpret_cast<float4*>(&op[(y0 + oy) * 56 + x0]) = o;
            }
        }
    }
}

// ---------------- launch ----------------
extern "C" void kernel_launch(void* const* d_in, const int* in_sizes, int n_in,
                              void* d_out, int out_size) {
    const float* x        = (const float*)d_in[0];
    const float* query    = (const float*)d_in[1];
    const float* Wk       = (const float*)d_in[2];
    const float* Wk_bias  = (const float*)d_in[3];
    const float* to_v_w   = (const float*)d_in[4];
    const float* to_v_b   = (const float*)d_in[5];
    const float* to_out_w = (const float*)d_in[6];
    const float* to_out_b = (const float*)d_in[7];
    const float* rpe      = (const float*)d_in[8];

    static float* pV = nullptr;
    static float* pOUTPRE = nullptr;
    if (!pV) {
        cudaGetSymbolAddress((void**)&pV, g_V);
        cudaGetSymbolAddress((void**)&pOUTPRE, g_OUTPRE);
    }

    prep_kernel<<<1, 384>>>(query, Wk, Wk_bias, rpe);

    dim3 ggrid((HW + BN - 1) / BN, CHID / BM, BATCH);  // (25, 3, 16)
    sgemm_fp16<<<ggrid, 128>>>(to_v_w, to_v_b, x, pV, CIN);

    cost_kernel<<<(BATCH * HW) / 256, 256>>>(x);

    dwconv_kernel<<<BATCH * HEADS * 4, 256>>>();

    sgemm_fp16<<<ggrid, 128>>>(to_out_w, to_out_b, pOUTPRE, (float*)d_out, CHID);
}

// round 10
// speedup vs baseline: 4.2456x; 1.0909x over previous
#include <cuda_runtime.h>
#include <cuda_fp16.h>
#include <math.h>
#include <stdint.h>

#define BATCH 16
#define CIN   192
#define CHID  384
#define HEADS 8
#define HDIM  48
#define IMG   56
#define HW    3136
#define KS    7

// ---------------- scratch ----------------
__device__ float g_qWkT[HEADS * CIN];
__device__ float g_biasq[HEADS];
__device__ float g_rpeexp[HEADS * 49];
__device__ __half g_V[(size_t)BATCH * CHID * HW];       // 38.5 MB
__device__ float  g_COSTE[(size_t)BATCH * HEADS * HW];  // 1.6 MB
__device__ __half g_OUTPRE[(size_t)BATCH * CHID * HW];  // 38.5 MB

__device__ __forceinline__ uint32_t smem_u32(const void* p) {
    uint32_t a;
    asm("{ .reg .u64 t; cvta.to.shared.u64 t, %1; cvt.u32.u64 %0, t; }" : "=r"(a) : "l"(p));
    return a;
}
__device__ __forceinline__ uint32_t packh2(float x, float y) {
    __half2 h = __floats2half2_rn(x, y);
    return *reinterpret_cast<uint32_t*>(&h);
}

// ---------------- K0: prep ----------------
__global__ void prep_kernel(const float* __restrict__ query,
                            const float* __restrict__ Wk,
                            const float* __restrict__ Wk_bias,
                            const float* __restrict__ rpe) {
    __shared__ float sq[CHID];
    __shared__ float snorm[HEADS];
    int tid = threadIdx.x;
    float inv = 1.0f / (sqrtf((float)HDIM) + 1e-6f);
    if (tid < CHID) sq[tid] = query[tid] * inv;
    __syncthreads();
    if (tid < HEADS) {
        float s = 0.f;
        for (int d = 0; d < HDIM; d++) { float v = sq[tid * HDIM + d]; s += v * v; }
        snorm[tid] = sqrtf(s) + 1e-6f;
    }
    __syncthreads();
    if (tid < CHID) sq[tid] = sq[tid] / snorm[tid / HDIM];
    __syncthreads();
    for (int e = tid; e < HEADS * CIN; e += blockDim.x) {
        int h = e / CIN, D = e % CIN;
        float s = 0.f;
        #pragma unroll 8
        for (int d = 0; d < HDIM; d++)
            s += sq[h * HDIM + d] * Wk[(size_t)D * CHID + h * HDIM + d];
        g_qWkT[e] = s;
    }
    if (tid < HEADS) {
        float s = 0.f;
        for (int d = 0; d < HDIM; d++)
            s += Wk_bias[tid * HDIM + d] * sq[tid * HDIM + d];
        g_biasq[tid] = s;
    }
    for (int e = tid; e < HEADS * 49; e += blockDim.x)
        g_rpeexp[e] = expf(rpe[e]);
}

// ---------------- shared GEMM config ----------------
#define BM 128
#define BN 128
#define BK 16
#define APB 48    // A row pitch bytes
#define BPB 272   // B row pitch bytes
#define ASTG (BM * APB)
#define BSTG (BK * BPB)

// ---------------- GEMM1: fp32 A/X -> half C (V projection) ----------------
__global__ __launch_bounds__(128, 2)
void sgemm_v(const float* __restrict__ A, const float* __restrict__ bias,
             const float* __restrict__ X, __half* __restrict__ C, int K) {
    const int b  = blockIdx.z;
    const int m0 = blockIdx.y * BM;
    const int n0 = blockIdx.x * BN;
    const float* Xb = X + (size_t)b * K * HW;
    __half* Cb = C + (size_t)b * CHID * HW;

    __shared__ __align__(16) char sA[2][ASTG];
    __shared__ __align__(16) char sB[2][BSTG];

    const int tid  = threadIdx.x;
    const int warp = tid >> 5;
    const int lane = tid & 31;
    const int quad = lane >> 2;
    const int qi   = lane & 3;
    const int m_base = (warp & 1) * 64;
    const int n_base = (warp >> 1) * 64;

    const uint32_t uA = smem_u32(&sA[0][0]);
    const uint32_t uB = smem_u32(&sB[0][0]);
    const uint32_t aAddrBase = uA + (uint32_t)(m_base + (lane & 15)) * APB + (uint32_t)((lane >> 4) * 8) * 2;
    const uint32_t bAddrBase = uB + (uint32_t)(lane & 15) * BPB + (uint32_t)(n_base + (lane >> 4) * 8) * 2;

    float acc[4][8][4];
    #pragma unroll
    for (int i = 0; i < 4; i++)
        #pragma unroll
        for (int j = 0; j < 8; j++)
            #pragma unroll
            for (int r = 0; r < 4; r++) acc[i][j][r] = 0.f;

    float4 aR[4], bR[4];
    auto load_regs = [&](int k0) {
        #pragma unroll
        for (int p = 0; p < 4; p++) {
            int c = p * 128 + tid;
            int m = c >> 2, kc = (c & 3) * 4;
            aR[p] = *reinterpret_cast<const float4*>(&A[(size_t)(m0 + m) * K + k0 + kc]);
        }
        #pragma unroll
        for (int p = 0; p < 4; p++) {
            int c = p * 128 + tid;
            int kr = c >> 5, nc = (c & 31) * 4;
            int col = n0 + nc; if (col > HW - 4) col = HW - 4;
            bR[p] = *reinterpret_cast<const float4*>(&Xb[(size_t)(k0 + kr) * HW + col]);
        }
    };
    auto store_stage = [&](int buf) {
        #pragma unroll
        for (int p = 0; p < 4; p++) {
            int c = p * 128 + tid;
            int m = c >> 2, kc = (c & 3) * 4;
            uint2 v = make_uint2(packh2(aR[p].x, aR[p].y), packh2(aR[p].z, aR[p].w));
            *reinterpret_cast<uint2*>(&sA[buf][m * APB + kc * 2]) = v;
        }
        #pragma unroll
        for (int p = 0; p < 4; p++) {
            int c = p * 128 + tid;
            int kr = c >> 5, nc = (c & 31) * 4;
            uint2 v = make_uint2(packh2(bR[p].x, bR[p].y), packh2(bR[p].z, bR[p].w));
            *reinterpret_cast<uint2*>(&sB[buf][kr * BPB + nc * 2]) = v;
        }
    };

    load_regs(0);
    store_stage(0);
    __syncthreads();

    const int T = K / BK;
    for (int t = 0; t < T; t++) {
        const int buf = t & 1;
        if (t + 1 < T) load_regs((t + 1) * BK);

        uint32_t af[4][4], bf[4][4];
        const uint32_t aOff = aAddrBase + (buf ? ASTG : 0);
        const uint32_t bOff = bAddrBase + (buf ? BSTG : 0);
        #pragma unroll
        for (int mt = 0; mt < 4; mt++)
            asm volatile("ldmatrix.sync.aligned.m8n8.x4.shared.b16 {%0,%1,%2,%3}, [%4];"
                : "=r"(af[mt][0]), "=r"(af[mt][1]), "=r"(af[mt][2]), "=r"(af[mt][3])
                : "r"(aOff + (uint32_t)(mt * 16) * APB));
        #pragma unroll
        for (int j = 0; j < 4; j++)
            asm volatile("ldmatrix.sync.aligned.m8n8.x4.trans.shared.b16 {%0,%1,%2,%3}, [%4];"
                : "=r"(bf[j][0]), "=r"(bf[j][1]), "=r"(bf[j][2]), "=r"(bf[j][3])
                : "r"(bOff + (uint32_t)(j * 16) * 2));
        #pragma unroll
        for (int mt = 0; mt < 4; mt++)
            #pragma unroll
            for (int nt = 0; nt < 8; nt++) {
                const int j = nt >> 1, h = (nt & 1) * 2;
                asm volatile(
                    "mma.sync.aligned.m16n8k16.row.col.f32.f16.f16.f32 "
                    "{%0,%1,%2,%3}, {%4,%5,%6,%7}, {%8,%9}, {%0,%1,%2,%3};"
                    : "+f"(acc[mt][nt][0]), "+f"(acc[mt][nt][1]),
                      "+f"(acc[mt][nt][2]), "+f"(acc[mt][nt][3])
                    : "r"(af[mt][0]), "r"(af[mt][1]), "r"(af[mt][2]), "r"(af[mt][3]),
                      "r"(bf[j][h]), "r"(bf[j][h + 1]));
            }

        if (t + 1 < T) { __syncthreads(); store_stage(1 - buf); }
        __syncthreads();
    }

    #pragma unroll
    for (int mt = 0; mt < 4; mt++) {
        const int r = m0 + m_base + mt * 16 + quad;
        const float bi0 = bias[r];
        const float bi1 = bias[r + 8];
        #pragma unroll
        for (int nt = 0; nt < 8; nt++) {
            const int c = n0 + n_base + nt * 8 + qi * 2;
            if (c < HW) {
                __half2 v0 = __floats2half2_rn(acc[mt][nt][0] + bi0, acc[mt][nt][1] + bi0);
                __half2 v1 = __floats2half2_rn(acc[mt][nt][2] + bi1, acc[mt][nt][3] + bi1);
                *reinterpret_cast<__half2*>(&Cb[(size_t)r * HW + c]) = v0;
                *reinterpret_cast<__half2*>(&Cb[(size_t)(r + 8) * HW + c]) = v1;
            }
        }
    }
}

// ---------------- GEMM2: fp32 A, half X -> fp32 C (output projection) --------
__global__ __launch_bounds__(128, 2)
void sgemm_out(const float* __restrict__ A, const float* __restrict__ bias,
               const __half* __restrict__ X, float* __restrict__ C, int K) {
    const int b  = blockIdx.z;
    const int m0 = blockIdx.y * BM;
    const int n0 = blockIdx.x * BN;
    const __half* Xb = X + (size_t)b * K * HW;
    float* Cb = C + (size_t)b * CHID * HW;

    __shared__ __align__(16) char sA[2][ASTG];
    __shared__ __align__(16) char sB[2][BSTG];

    const int tid  = threadIdx.x;
    const int warp = tid >> 5;
    const int lane = tid & 31;
    const int quad = lane >> 2;
    const int qi   = lane & 3;
    const int m_base = (warp & 1) * 64;
    const int n_base = (warp >> 1) * 64;

    const uint32_t uA = smem_u32(&sA[0][0]);
    const uint32_t uB = smem_u32(&sB[0][0]);
    const uint32_t aAddrBase = uA + (uint32_t)(m_base + (lane & 15)) * APB + (uint32_t)((lane >> 4) * 8) * 2;
    const uint32_t bAddrBase = uB + (uint32_t)(lane & 15) * BPB + (uint32_t)(n_base + (lane >> 4) * 8) * 2;

    float acc[4][8][4];
    #pragma unroll
    for (int i = 0; i < 4; i++)
        #pragma unroll
        for (int j = 0; j < 8; j++)
            #pragma unroll
            for (int r = 0; r < 4; r++) acc[i][j][r] = 0.f;

    float4 aR[4];
    uint4 bR[2];
    auto load_regs = [&](int k0) {
        #pragma unroll
        for (int p = 0; p < 4; p++) {
            int c = p * 128 + tid;
            int m = c >> 2, kc = (c & 3) * 4;
            aR[p] = *reinterpret_cast<const float4*>(&A[(size_t)(m0 + m) * K + k0 + kc]);
        }
        // B: 16 rows x 128 half = 256 x 16B chunks; 2 per thread, raw copy
        #pragma unroll
        for (int p = 0; p < 2; p++) {
            int c = p * 128 + tid;
            int kr = c >> 4, nc = (c & 15) * 8;
            int col = n0 + nc; if (col > HW - 8) col = HW - 8;
            bR[p] = *reinterpret_cast<const uint4*>(&Xb[(size_t)(k0 + kr) * HW + col]);
        }
    };
    auto store_stage = [&](int buf) {
        #pragma unroll
        for (int p = 0; p < 4; p++) {
            int c = p * 128 + tid;
            int m = c >> 2, kc = (c & 3) * 4;
            uint2 v = make_uint2(packh2(aR[p].x, aR[p].y), packh2(aR[p].z, aR[p].w));
            *reinterpret_cast<uint2*>(&sA[buf][m * APB + kc * 2]) = v;
        }
        #pragma unroll
        for (int p = 0; p < 2; p++) {
            int c = p * 128 + tid;
            int kr = c >> 4, nc = (c & 15) * 8;
            *reinterpret_cast<uint4*>(&sB[buf][kr * BPB + nc * 2]) = bR[p];
        }
    };

    load_regs(0);
    store_stage(0);
    __syncthreads();

    const int T = K / BK;
    for (int t = 0; t < T; t++) {
        const int buf = t & 1;
        if (t + 1 < T) load_regs((t + 1) * BK);

        uint32_t af[4][4], bf[4][4];
        const uint32_t aOff = aAddrBase + (buf ? ASTG : 0);
        const uint32_t bOff = bAddrBase + (buf ? BSTG : 0);
        #pragma unroll
        for (int mt = 0; mt < 4; mt++)
            asm volatile("ldmatrix.sync.aligned.m8n8.x4.shared.b16 {%0,%1,%2,%3}, [%4];"
                : "=r"(af[mt][0]), "=r"(af[mt][1]), "=r"(af[mt][2]), "=r"(af[mt][3])
                : "r"(aOff + (uint32_t)(mt * 16) * APB));
        #pragma unroll
        for (int j = 0; j < 4; j++)
            asm volatile("ldmatrix.sync.aligned.m8n8.x4.trans.shared.b16 {%0,%1,%2,%3}, [%4];"
                : "=r"(bf[j][0]), "=r"(bf[j][1]), "=r"(bf[j][2]), "=r"(bf[j][3])
                : "r"(bOff + (uint32_t)(j * 16) * 2));
        #pragma unroll
        for (int mt = 0; mt < 4; mt++)
            #pragma unroll
            for (int nt = 0; nt < 8; nt++) {
                const int j = nt >> 1, h = (nt & 1) * 2;
                asm volatile(
                    "mma.sync.aligned.m16n8k16.row.col.f32.f16.f16.f32 "
                    "{%0,%1,%2,%3}, {%4,%5,%6,%7}, {%8,%9}, {%0,%1,%2,%3};"
                    : "+f"(acc[mt][nt][0]), "+f"(acc[mt][nt][1]),
                      "+f"(acc[mt][nt][2]), "+f"(acc[mt][nt][3])
                    : "r"(af[mt][0]), "r"(af[mt][1]), "r"(af[mt][2]), "r"(af[mt][3]),
                      "r"(bf[j][h]), "r"(bf[j][h + 1]));
            }

        if (t + 1 < T) { __syncthreads(); store_stage(1 - buf); }
        __syncthreads();
    }

    #pragma unroll
    for (int mt = 0; mt < 4; mt++) {
        const int r = m0 + m_base + mt * 16 + quad;
        const float bi0 = bias[r];
        const float bi1 = bias[r + 8];
        #pragma unroll
        for (int nt = 0; nt < 8; nt++) {
            const int c = n0 + n_base + nt * 8 + qi * 2;
            if (c < HW) {
                float2 v0 = make_float2(acc[mt][nt][0] + bi0, acc[mt][nt][1] + bi0);
                float2 v1 = make_float2(acc[mt][nt][2] + bi1, acc[mt][nt][3] + bi1);
                *reinterpret_cast<float2*>(&Cb[(size_t)r * HW + c]) = v0;
                *reinterpret_cast<float2*>(&Cb[(size_t)(r + 8) * HW + c]) = v1;
            }
        }
    }
}

// ---------------- cost kernel ----------------
__global__ __launch_bounds__(256)
void cost_kernel(const float* __restrict__ x) {
    __shared__ float4 sW4[HEADS * CIN / 4];
    __shared__ float sb[HEADS];
    int tid = threadIdx.x;
    const float4* gW4 = reinterpret_cast<const float4*>(g_qWkT);
    for (int i = tid; i < HEADS * CIN / 4; i += 256) sW4[i] = gW4[i];
    if (tid < HEADS) sb[tid] = g_biasq[tid];
    __syncthreads();

    int idx = blockIdx.x * 256 + tid;
    if (idx >= BATCH * HW) return;
    int b = idx / HW, hw = idx % HW;
    const float* xb = x + (size_t)b * CIN * HW + hw;
    float acc[HEADS] = {};
    for (int D4 = 0; D4 < CIN / 4; D4++) {
        float x0 = xb[(size_t)(D4 * 4 + 0) * HW];
        float x1 = xb[(size_t)(D4 * 4 + 1) * HW];
        float x2 = xb[(size_t)(D4 * 4 + 2) * HW];
        float x3 = xb[(size_t)(D4 * 4 + 3) * HW];
        #pragma unroll
        for (int h = 0; h < HEADS; h++) {
            float4 w = sW4[h * (CIN / 4) + D4];
            acc[h] += x0 * w.x + x1 * w.y + x2 * w.z + x3 * w.w;
        }
    }
    float* cb = g_COSTE + (size_t)b * HEADS * HW + hw;
    #pragma unroll
    for (int h = 0; h < HEADS; h++)
        cb[(size_t)h * HW] = expf(acc[h] + sb[h]);
}

// ---------------- dwconv kernel ----------------
#define DP 68

__global__ __launch_bounds__(256)
void dwconv_kernel() {
    const int bidx = blockIdx.x;
    const int cg = bidx & 3;
    const int head = (bidx >> 2) & 7;
    const int b = bidx >> 5;

    __shared__ __align__(16) float sc[62 * DP];
    __shared__ __align__(16) float scv[62 * DP];

    const int tid = threadIdx.x;

    float wr[49];
    #pragma unroll
    for (int i = 0; i < 49; i++) wr[i] = g_rpeexp[head * 49 + i];

    const float* cp = g_COSTE + ((size_t)b * HEADS + head) * HW;
    for (int i = tid; i < 62 * DP; i += 256) {
        int r = i / DP, c = i % DP;
        int y = r - 3, x = c - 4;
        float v = 0.f;
        if ((unsigned)y < 56u && (unsigned)x < 56u) v = cp[y * 56 + x];
        sc[i] = v;
        scv[i] = 0.f;
    }
    __syncthreads();

    const int y0 = (tid / 14) * 4;
    const int x0 = (tid % 14) * 4;
    const bool active = tid < 196;

    float4 rden[4];
    if (active) {
        float acc[4][4] = {};
        #pragma unroll
        for (int i = 0; i < 10; i++) {
            float r[10];
            #pragma unroll
            for (int j = 0; j < 10; j++) r[j] = sc[(y0 + i) * DP + x0 + 1 + j];
            #pragma unroll
            for (int oy = 0; oy < 4; oy++) {
                const int wi = i - oy;
                if (wi >= 0 && wi < 7) {
                    #pragma unroll
                    for (int j = 0; j < 7; j++) {
                        float wv = wr[wi * 7 + j];
                        acc[oy][0] += wv * r[j];
                        acc[oy][1] += wv * r[j + 1];
                        acc[oy][2] += wv * r[j + 2];
                        acc[oy][3] += wv * r[j + 3];
                    }
                }
            }
        }
        #pragma unroll
        for (int oy = 0; oy < 4; oy++)
            rden[oy] = make_float4(1.f / acc[oy][0], 1.f / acc[oy][1],
                                   1.f / acc[oy][2], 1.f / acc[oy][3]);
    }

    for (int c = 0; c < 12; c++) {
        const int ch = head * HDIM + cg * 12 + c;
        const __half* vp = g_V + ((size_t)b * CHID + ch) * HW;
        __syncthreads();
        for (int i = tid; i < 784; i += 256) {
            int y = i / 14, c4 = (i % 14) * 4;
            uint2 raw = *reinterpret_cast<const uint2*>(&vp[y * 56 + c4]);
            float2 f0 = __half22float2(*reinterpret_cast<__half2*>(&raw.x));
            float2 f1 = __half22float2(*reinterpret_cast<__half2*>(&raw.y));
            float4 s = *reinterpret_cast<const float4*>(&sc[(y + 3) * DP + 4 + c4]);
            float4 o = make_float4(f0.x * s.x, f0.y * s.y, f1.x * s.z, f1.y * s.w);
            *reinterpret_cast<float4*>(&scv[(y + 3) * DP + 4 + c4]) = o;
        }
        __syncthreads();
        if (active) {
            float acc[4][4] = {};
            #pragma unroll
            for (int i = 0; i < 10; i++) {
                float r[10];
                #pragma unroll
                for (int j = 0; j < 10; j++) r[j] = scv[(y0 + i) * DP + x0 + 1 + j];
                #pragma unroll
                for (int oy = 0; oy < 4; oy++) {
                    const int wi = i - oy;
                    if (wi >= 0 && wi < 7) {
                        #pragma unroll
                        for (int j = 0; j < 7; j++) {
                            float wv = wr[wi * 7 + j];
                            acc[oy][0] += wv * r[j];
                            acc[oy][1] += wv * r[j + 1];
                            acc[oy][2] += wv * r[j + 2];
                            acc[oy][3] += wv * r[j + 3];
                        }
                    }
                }
            }
            __half* op = g_OUTPRE + ((size_t)b * CHID + ch) * HW;
            #pragma unroll
            for (int oy = 0; oy < 4; oy++) {
                __half2 o0 = __floats2half2_rn(acc[oy][0] * rden[oy].x, acc[oy][1] * rden[oy].y);
                __half2 o1 = __floats2half2_rn(acc[oy][2] * rden[oy].z, acc[oy][3] * rden[oy].w);
                uint2 pk = make_uint2(*reinterpret_cast<uint32_t*>(&o0),
                                      *reinterpret_cast<uint32_t*>(&o1));
                *reinterpret_cast<uint2*>(&op[(y0 + oy) * 56 + x0]) = pk;
            }
        }
    }
}

// ---------------- launch ----------------
extern "C" void kernel_launch(void* const* d_in, const int* in_sizes, int n_in,
                              void* d_out, int out_size) {
    const float* x        = (const float*)d_in[0];
    const float* query    = (const float*)d_in[1];
    const float* Wk       = (const float*)d_in[2];
    const float* Wk_bias  = (const float*)d_in[3];
    const float* to_v_w   = (const float*)d_in[4];
    const float* to_v_b   = (const float*)d_in[5];
    const float* to_out_w = (const float*)d_in[6];
    const float* to_out_b = (const float*)d_in[7];
    const float* rpe      = (const float*)d_in[8];

    static __half* pV = nullptr;
    static __half* pOUTPRE = nullptr;
    if (!pV) {
        cudaGetSymbolAddress((void**)&pV, g_V);
        cudaGetSymbolAddress((void**)&pOUTPRE, g_OUTPRE);
    }

    prep_kernel<<<1, 384>>>(query, Wk, Wk_bias, rpe);

    dim3 ggrid((HW + BN - 1) / BN, CHID / BM, BATCH);  // (25, 3, 16)
    sgemm_v<<<ggrid, 128>>>(to_v_w, to_v_b, x, pV, CIN);

    cost_kernel<<<(BATCH * HW) / 256, 256>>>(x);

    dwconv_kernel<<<BATCH * HEADS * 4, 256>>>();

    sgemm_out<<<ggrid, 128>>>(to_out_w, to_out_b, pOUTPRE, (float*)d_out, CHID);
}

// round 13
// speedup vs baseline: 4.5653x; 1.0753x over previous
#include <cuda_runtime.h>
#include <cuda_fp16.h>
#include <math.h>
#include <stdint.h>

#define BATCH 16
#define CIN   192
#define CHID  384
#define HEADS 8
#define HDIM  48
#define IMG   56
#define HW    3136
#define KS    7

// ---------------- scratch ----------------
__device__ float g_qWkT[HEADS * CIN];
__device__ float g_biasq[HEADS];
__device__ float g_rpeexp[HEADS * 49];
__device__ __half g_wvh[CHID * CIN];                    // half to_v_w
__device__ __half g_woh[CHID * CHID];                   // half to_out_w
__device__ __half g_V[(size_t)BATCH * CHID * HW];       // 38.5 MB
__device__ float  g_COSTE[(size_t)BATCH * HEADS * HW];  // 1.6 MB
__device__ __half g_OUTPRE[(size_t)BATCH * CHID * HW];  // 38.5 MB

__device__ __forceinline__ uint32_t smem_u32(const void* p) {
    uint32_t a;
    asm("{ .reg .u64 t; cvta.to.shared.u64 t, %1; cvt.u32.u64 %0, t; }" : "=r"(a) : "l"(p));
    return a;
}
__device__ __forceinline__ uint32_t packh2(float x, float y) {
    __half2 h = __floats2half2_rn(x, y);
    return *reinterpret_cast<uint32_t*>(&h);
}

// ---------------- K0: prep ----------------
__global__ void prep_kernel(const float* __restrict__ query,
                            const float* __restrict__ Wk,
                            const float* __restrict__ Wk_bias,
                            const float* __restrict__ rpe) {
    __shared__ float sq[CHID];
    __shared__ float snorm[HEADS];
    int tid = threadIdx.x;
    float inv = 1.0f / (sqrtf((float)HDIM) + 1e-6f);
    if (tid < CHID) sq[tid] = query[tid] * inv;
    __syncthreads();
    if (tid < HEADS) {
        float s = 0.f;
        for (int d = 0; d < HDIM; d++) { float v = sq[tid * HDIM + d]; s += v * v; }
        snorm[tid] = sqrtf(s) + 1e-6f;
    }
    __syncthreads();
    if (tid < CHID) sq[tid] = sq[tid] / snorm[tid / HDIM];
    __syncthreads();
    for (int e = tid; e < HEADS * CIN; e += blockDim.x) {
        int h = e / CIN, D = e % CIN;
        float s = 0.f;
        #pragma unroll 8
        for (int d = 0; d < HDIM; d++)
            s += sq[h * HDIM + d] * Wk[(size_t)D * CHID + h * HDIM + d];
        g_qWkT[e] = s;
    }
    if (tid < HEADS) {
        float s = 0.f;
        for (int d = 0; d < HDIM; d++)
            s += Wk_bias[tid * HDIM + d] * sq[tid * HDIM + d];
        g_biasq[tid] = s;
    }
    for (int e = tid; e < HEADS * 49; e += blockDim.x)
        g_rpeexp[e] = expf(rpe[e]);
}

// ---------------- weight conversion ----------------
__global__ __launch_bounds__(256)
void convw_kernel(const float* __restrict__ wv, const float* __restrict__ wo) {
    int gid = blockIdx.x * 256 + threadIdx.x;
    int nth = gridDim.x * 256;
    for (int i = gid; i < CHID * CIN; i += nth) g_wvh[i] = __float2half_rn(wv[i]);
    for (int i = gid; i < CHID * CHID; i += nth) g_woh[i] = __float2half_rn(wo[i]);
}

// ---------------- shared GEMM config ----------------
#define BM 128
#define BN 128

// ---------------- GEMM1: half A(weights), fp32 B(x) -> half C (V) ----------
#define BK1 16
#define APB1 48
#define BPB 272
#define ASTG1 (BM * APB1)
#define BSTG1 (BK1 * BPB)

__global__ __launch_bounds__(128, 2)
void sgemm_v(const __half* __restrict__ A, const float* __restrict__ bias,
             const float* __restrict__ X, __half* __restrict__ C) {
    const int K = CIN;
    const int b  = blockIdx.z;
    const int m0 = blockIdx.y * BM;
    const int n0 = blockIdx.x * BN;
    const float* Xb = X + (size_t)b * K * HW;
    __half* Cb = C + (size_t)b * CHID * HW;

    __shared__ __align__(16) char sA[2][ASTG1];
    __shared__ __align__(16) char sB[2][BSTG1];

    const int tid  = threadIdx.x;
    const int warp = tid >> 5;
    const int lane = tid & 31;
    const int quad = lane >> 2;
    const int qi   = lane & 3;
    const int m_base = (warp & 1) * 64;
    const int n_base = (warp >> 1) * 64;

    const uint32_t uA = smem_u32(&sA[0][0]);
    const uint32_t uB = smem_u32(&sB[0][0]);
    const uint32_t aAddrBase = uA + (uint32_t)(m_base + (lane & 15)) * APB1 + (uint32_t)((lane >> 4) * 8) * 2;
    const uint32_t bAddrBase = uB + (uint32_t)(lane & 15) * BPB + (uint32_t)(n_base + (lane >> 4) * 8) * 2;

    float acc[4][8][4];
    #pragma unroll
    for (int i = 0; i < 4; i++)
        #pragma unroll
        for (int j = 0; j < 8; j++)
            #pragma unroll
            for (int r = 0; r < 4; r++) acc[i][j][r] = 0.f;

    uint4 aR[2];
    float4 bR[4];
    auto load_regs = [&](int k0) {
        #pragma unroll
        for (int p = 0; p < 2; p++) {
            int c = p * 128 + tid;
            int m = c >> 1, j = c & 1;
            aR[p] = *reinterpret_cast<const uint4*>(&A[(size_t)(m0 + m) * K + k0 + j * 8]);
        }
        #pragma unroll
        for (int p = 0; p < 4; p++) {
            int c = p * 128 + tid;
            int kr = c >> 5, nc = (c & 31) * 4;
            int col = n0 + nc; if (col > HW - 4) col = HW - 4;
            bR[p] = *reinterpret_cast<const float4*>(&Xb[(size_t)(k0 + kr) * HW + col]);
        }
    };
    auto store_stage = [&](int buf) {
        #pragma unroll
        for (int p = 0; p < 2; p++) {
            int c = p * 128 + tid;
            int m = c >> 1, j = c & 1;
            *reinterpret_cast<uint4*>(&sA[buf][m * APB1 + j * 16]) = aR[p];
        }
        #pragma unroll
        for (int p = 0; p < 4; p++) {
            int c = p * 128 + tid;
            int kr = c >> 5, nc = (c & 31) * 4;
            uint2 v = make_uint2(packh2(bR[p].x, bR[p].y), packh2(bR[p].z, bR[p].w));
            *reinterpret_cast<uint2*>(&sB[buf][kr * BPB + nc * 2]) = v;
        }
    };

    load_regs(0);
    store_stage(0);
    __syncthreads();

    const int T = K / BK1;
    for (int t = 0; t < T; t++) {
        const int buf = t & 1;
        if (t + 1 < T) load_regs((t + 1) * BK1);

        uint32_t af[4][4], bf[4][4];
        const uint32_t aOff = aAddrBase + (buf ? ASTG1 : 0);
        const uint32_t bOff = bAddrBase + (buf ? BSTG1 : 0);
        #pragma unroll
        for (int mt = 0; mt < 4; mt++)
            asm volatile("ldmatrix.sync.aligned.m8n8.x4.shared.b16 {%0,%1,%2,%3}, [%4];"
                : "=r"(af[mt][0]), "=r"(af[mt][1]), "=r"(af[mt][2]), "=r"(af[mt][3])
                : "r"(aOff + (uint32_t)(mt * 16) * APB1));
        #pragma unroll
        for (int j = 0; j < 4; j++)
            asm volatile("ldmatrix.sync.aligned.m8n8.x4.trans.shared.b16 {%0,%1,%2,%3}, [%4];"
                : "=r"(bf[j][0]), "=r"(bf[j][1]), "=r"(bf[j][2]), "=r"(bf[j][3])
                : "r"(bOff + (uint32_t)(j * 16) * 2));
        #pragma unroll
        for (int mt = 0; mt < 4; mt++)
            #pragma unroll
            for (int nt = 0; nt < 8; nt++) {
                const int j = nt >> 1, h = (nt & 1) * 2;
                asm volatile(
                    "mma.sync.aligned.m16n8k16.row.col.f32.f16.f16.f32 "
                    "{%0,%1,%2,%3}, {%4,%5,%6,%7}, {%8,%9}, {%0,%1,%2,%3};"
                    : "+f"(acc[mt][nt][0]), "+f"(acc[mt][nt][1]),
                      "+f"(acc[mt][nt][2]), "+f"(acc[mt][nt][3])
                    : "r"(af[mt][0]), "r"(af[mt][1]), "r"(af[mt][2]), "r"(af[mt][3]),
                      "r"(bf[j][h]), "r"(bf[j][h + 1]));
            }

        if (t + 1 < T) store_stage(1 - buf);
        __syncthreads();
    }

    #pragma unroll
    for (int mt = 0; mt < 4; mt++) {
        const int r = m0 + m_base + mt * 16 + quad;
        const float bi0 = bias[r];
        const float bi1 = bias[r + 8];
        #pragma unroll
        for (int nt = 0; nt < 8; nt++) {
            const int c = n0 + n_base + nt * 8 + qi * 2;
            if (c < HW) {
                __half2 v0 = __floats2half2_rn(acc[mt][nt][0] + bi0, acc[mt][nt][1] + bi0);
                __half2 v1 = __floats2half2_rn(acc[mt][nt][2] + bi1, acc[mt][nt][3] + bi1);
                *reinterpret_cast<__half2*>(&Cb[(size_t)r * HW + c]) = v0;
                *reinterpret_cast<__half2*>(&Cb[(size_t)(r + 8) * HW + c]) = v1;
            }
        }
    }
}

// ---------------- GEMM2: half A(weights), half B(OUTPRE) -> fp32 C ----------
#define BK2 32
#define APB2 80     // 64B data + 16B pad; conflict-free for ldmatrix
#define ASTG2 (BM * APB2)   // 10240
#define BSTG2 (BK2 * BPB)   // 8704

__global__ __launch_bounds__(128, 2)
void sgemm_out(const __half* __restrict__ A, const float* __restrict__ bias,
               const __half* __restrict__ X, float* __restrict__ C) {
    const int K = CHID;
    const int b  = blockIdx.z;
    const int m0 = blockIdx.y * BM;
    const int n0 = blockIdx.x * BN;
    const __half* Xb = X + (size_t)b * K * HW;
    float* Cb = C + (size_t)b * CHID * HW;

    __shared__ __align__(16) char sA[2][ASTG2];
    __shared__ __align__(16) char sB[2][BSTG2];

    const int tid  = threadIdx.x;
    const int warp = tid >> 5;
    const int lane = tid & 31;
    const int quad = lane >> 2;
    const int qi   = lane & 3;
    const int m_base = (warp & 1) * 64;
    const int n_base = (warp >> 1) * 64;

    const uint32_t uA = smem_u32(&sA[0][0]);
    const uint32_t uB = smem_u32(&sB[0][0]);
    const uint32_t aAddrBase = uA + (uint32_t)(m_base + (lane & 15)) * APB2 + (uint32_t)((lane >> 4) * 8) * 2;
    const uint32_t bAddrBase = uB + (uint32_t)(lane & 15) * BPB + (uint32_t)(n_base + (lane >> 4) * 8) * 2;

    float acc[4][8][4];
    #pragma unroll
    for (int i = 0; i < 4; i++)
        #pragma unroll
        for (int j = 0; j < 8; j++)
            #pragma unroll
            for (int r = 0; r < 4; r++) acc[i][j][r] = 0.f;

    uint4 aR[4], bR[4];
    auto load_regs = [&](int k0) {
        #pragma unroll
        for (int p = 0; p < 4; p++) {
            int c = p * 128 + tid;
            int m = c >> 2, j = c & 3;
            aR[p] = *reinterpret_cast<const uint4*>(&A[(size_t)(m0 + m) * K + k0 + j * 8]);
        }
        #pragma unroll
        for (int p = 0; p < 4; p++) {
            int c = p * 128 + tid;
            int kr = c >> 4, nc = (c & 15) * 8;
            int col = n0 + nc; if (col > HW - 8) col = HW - 8;
            bR[p] = *reinterpret_cast<const uint4*>(&Xb[(size_t)(k0 + kr) * HW + col]);
        }
    };
    auto store_stage = [&](int buf) {
        #pragma unroll
        for (int p = 0; p < 4; p++) {
            int c = p * 128 + tid;
            int m = c >> 2, j = c & 3;
            *reinterpret_cast<uint4*>(&sA[buf][m * APB2 + j * 16]) = aR[p];
        }
        #pragma unroll
        for (int p = 0; p < 4; p++) {
            int c = p * 128 + tid;
            int kr = c >> 4, nc = (c & 15) * 8;
            *reinterpret_cast<uint4*>(&sB[buf][kr * BPB + nc * 2]) = bR[p];
        }
    };

    load_regs(0);
    store_stage(0);
    __syncthreads();

    const int T = K / BK2;
    for (int t = 0; t < T; t++) {
        const int buf = t & 1;
        if (t + 1 < T) load_regs((t + 1) * BK2);

        const uint32_t aOff = aAddrBase + (buf ? ASTG2 : 0);
        const uint32_t bOff = bAddrBase + (buf ? BSTG2 : 0);
        #pragma unroll
        for (int h = 0; h < 2; h++) {
            uint32_t af[4][4], bf[4][4];
            #pragma unroll
            for (int mt = 0; mt < 4; mt++)
                asm volatile("ldmatrix.sync.aligned.m8n8.x4.shared.b16 {%0,%1,%2,%3}, [%4];"
                    : "=r"(af[mt][0]), "=r"(af[mt][1]), "=r"(af[mt][2]), "=r"(af[mt][3])
                    : "r"(aOff + (uint32_t)(mt * 16) * APB2 + (uint32_t)(h * 32)));
            #pragma unroll
            for (int j = 0; j < 4; j++)
                asm volatile("ldmatrix.sync.aligned.m8n8.x4.trans.shared.b16 {%0,%1,%2,%3}, [%4];"
                    : "=r"(bf[j][0]), "=r"(bf[j][1]), "=r"(bf[j][2]), "=r"(bf[j][3])
                    : "r"(bOff + (uint32_t)(j * 16) * 2 + (uint32_t)(h * 16) * BPB));
            #pragma unroll
            for (int mt = 0; mt < 4; mt++)
                #pragma unroll
                for (int nt = 0; nt < 8; nt++) {
                    const int j = nt >> 1, hh = (nt & 1) * 2;
                    asm volatile(
                        "mma.sync.aligned.m16n8k16.row.col.f32.f16.f16.f32 "
                        "{%0,%1,%2,%3}, {%4,%5,%6,%7}, {%8,%9}, {%0,%1,%2,%3};"
                        : "+f"(acc[mt][nt][0]), "+f"(acc[mt][nt][1]),
                          "+f"(acc[mt][nt][2]), "+f"(acc[mt][nt][3])
                        : "r"(af[mt][0]), "r"(af[mt][1]), "r"(af[mt][2]), "r"(af[mt][3]),
                          "r"(bf[j][hh]), "r"(bf[j][hh + 1]));
                }
        }

        if (t + 1 < T) store_stage(1 - buf);
        __syncthreads();
    }

    #pragma unroll
    for (int mt = 0; mt < 4; mt++) {
        const int r = m0 + m_base + mt * 16 + quad;
        const float bi0 = bias[r];
        const float bi1 = bias[r + 8];
        #pragma unroll
        for (int nt = 0; nt < 8; nt++) {
            const int c = n0 + n_base + nt * 8 + qi * 2;
            if (c < HW) {
                float2 v0 = make_float2(acc[mt][nt][0] + bi0, acc[mt][nt][1] + bi0);
                float2 v1 = make_float2(acc[mt][nt][2] + bi1, acc[mt][nt][3] + bi1);
                *reinterpret_cast<float2*>(&Cb[(size_t)r * HW + c]) = v0;
                *reinterpret_cast<float2*>(&Cb[(size_t)(r + 8) * HW + c]) = v1;
            }
        }
    }
}

// ---------------- cost kernel ----------------
__global__ __launch_bounds__(256)
void cost_kernel(const float* __restrict__ x) {
    __shared__ float4 sW4[HEADS * CIN / 4];
    __shared__ float sb[HEADS];
    int tid = threadIdx.x;
    const float4* gW4 = reinterpret_cast<const float4*>(g_qWkT);
    for (int i = tid; i < HEADS * CIN / 4; i += 256) sW4[i] = gW4[i];
    if (tid < HEADS) sb[tid] = g_biasq[tid];
    __syncthreads();

    int idx = blockIdx.x * 256 + tid;
    if (idx >= BATCH * HW) return;
    int b = idx / HW, hw = idx % HW;
    const float* xb = x + (size_t)b * CIN * HW + hw;
    float acc[HEADS] = {};
    for (int D4 = 0; D4 < CIN / 4; D4++) {
        float x0 = xb[(size_t)(D4 * 4 + 0) * HW];
        float x1 = xb[(size_t)(D4 * 4 + 1) * HW];
        float x2 = xb[(size_t)(D4 * 4 + 2) * HW];
        float x3 = xb[(size_t)(D4 * 4 + 3) * HW];
        #pragma unroll
        for (int h = 0; h < HEADS; h++) {
            float4 w = sW4[h * (CIN / 4) + D4];
            acc[h] += x0 * w.x + x1 * w.y + x2 * w.z + x3 * w.w;
        }
    }
    float* cb = g_COSTE + (size_t)b * HEADS * HW + hw;
    #pragma unroll
    for (int h = 0; h < HEADS; h++)
        cb[(size_t)h * HW] = expf(acc[h] + sb[h]);
}

// ---------------- dwconv kernel (vectorized windows) ----------------
#define DP 68

__global__ __launch_bounds__(256)
void dwconv_kernel() {
    const int bidx = blockIdx.x;
    const int cg = bidx & 3;
    const int head = (bidx >> 2) & 7;
    const int b = bidx >> 5;

    __shared__ __align__(16) float sc[62 * DP];
    __shared__ __align__(16) float scv[62 * DP];

    const int tid = threadIdx.x;

    float wr[49];
    #pragma unroll
    for (int i = 0; i < 49; i++) wr[i] = g_rpeexp[head * 49 + i];

    const float* cp = g_COSTE + ((size_t)b * HEADS + head) * HW;
    for (int i = tid; i < 62 * DP; i += 256) {
        int r = i / DP, c = i % DP;
        int y = r - 3, x = c - 4;
        float v = 0.f;
        if ((unsigned)y < 56u && (unsigned)x < 56u) v = cp[y * 56 + x];
        sc[i] = v;
        scv[i] = 0.f;
    }
    __syncthreads();

    const int y0 = (tid / 14) * 4;
    const int x0 = (tid % 14) * 4;
    const bool active = tid < 196;

    float4 rden[4];
    if (active) {
        float acc[4][4] = {};
        #pragma unroll
        for (int i = 0; i < 10; i++) {
            const float* base = &sc[(y0 + i) * DP + x0];
            float4 q0 = *reinterpret_cast<const float4*>(base);
            float4 q1 = *reinterpret_cast<const float4*>(base + 4);
            float4 q2 = *reinterpret_cast<const float4*>(base + 8);
            float r[12] = {q0.x, q0.y, q0.z, q0.w, q1.x, q1.y, q1.z, q1.w,
                           q2.x, q2.y, q2.z, q2.w};
            #pragma unroll
            for (int oy = 0; oy < 4; oy++) {
                const int wi = i - oy;
                if (wi >= 0 && wi < 7) {
                    #pragma unroll
                    for (int j = 0; j < 7; j++) {
                        float wv = wr[wi * 7 + j];
                        acc[oy][0] += wv * r[j + 1];
                        acc[oy][1] += wv * r[j + 2];
                        acc[oy][2] += wv * r[j + 3];
                        acc[oy][3] += wv * r[j + 4];
                    }
                }
            }
        }
        #pragma unroll
        for (int oy = 0; oy < 4; oy++)
            rden[oy] = make_float4(1.f / acc[oy][0], 1.f / acc[oy][1],
                                   1.f / acc[oy][2], 1.f / acc[oy][3]);
    }

    for (int c = 0; c < 12; c++) {
        const int ch = head * HDIM + cg * 12 + c;
        const __half* vp = g_V + ((size_t)b * CHID + ch) * HW;
        __syncthreads();
        for (int i = tid; i < 784; i += 256) {
            int y = i / 14, c4 = (i % 14) * 4;
            uint2 raw = *reinterpret_cast<const uint2*>(&vp[y * 56 + c4]);
            float2 f0 = __half22float2(*reinterpret_cast<__half2*>(&raw.x));
            float2 f1 = __half22float2(*reinterpret_cast<__half2*>(&raw.y));
            float4 s = *reinterpret_cast<const float4*>(&sc[(y + 3) * DP + 4 + c4]);
            float4 o = make_float4(f0.x * s.x, f0.y * s.y, f1.x * s.z, f1.y * s.w);
            *reinterpret_cast<float4*>(&scv[(y + 3) * DP + 4 + c4]) = o;
        }
        __syncthreads();
        if (active) {
            float acc[4][4] = {};
            #pragma unroll
            for (int i = 0; i < 10; i++) {
                const float* base = &scv[(y0 + i) * DP + x0];
                float4 q0 = *reinterpret_cast<const float4*>(base);
                float4 q1 = *reinterpret_cast<const float4*>(base + 4);
                float4 q2 = *reinterpret_cast<const float4*>(base + 8);
                float r[12] = {q0.x, q0.y, q0.z, q0.w, q1.x, q1.y, q1.z, q1.w,
                               q2.x, q2.y, q2.z, q2.w};
                #pragma unroll
                for (int oy = 0; oy < 4; oy++) {
                    const int wi = i - oy;
                    if (wi >= 0 && wi < 7) {
                        #pragma unroll
                        for (int j = 0; j < 7; j++) {
                            float wv = wr[wi * 7 + j];
                            acc[oy][0] += wv * r[j + 1];
                            acc[oy][1] += wv * r[j + 2];
                            acc[oy][2] += wv * r[j + 3];
                            acc[oy][3] += wv * r[j + 4];
                        }
                    }
                }
            }
            __half* op = g_OUTPRE + ((size_t)b * CHID + ch) * HW;
            #pragma unroll
            for (int oy = 0; oy < 4; oy++) {
                __half2 o0 = __floats2half2_rn(acc[oy][0] * rden[oy].x, acc[oy][1] * rden[oy].y);
                __half2 o1 = __floats2half2_rn(acc[oy][2] * rden[oy].z, acc[oy][3] * rden[oy].w);
                uint2 pk = make_uint2(*reinterpret_cast<uint32_t*>(&o0),
                                      *reinterpret_cast<uint32_t*>(&o1));
                *reinterpret_cast<uint2*>(&op[(y0 + oy) * 56 + x0]) = pk;
            }
        }
    }
}

// ---------------- launch ----------------
extern "C" void kernel_launch(void* const* d_in, const int* in_sizes, int n_in,
                              void* d_out, int out_size) {
    const float* x        = (const float*)d_in[0];
    const float* query    = (const float*)d_in[1];
    const float* Wk       = (const float*)d_in[2];
    const float* Wk_bias  = (const float*)d_in[3];
    const float* to_v_w   = (const float*)d_in[4];
    const float* to_v_b   = (const float*)d_in[5];
    const float* to_out_w = (const float*)d_in[6];
    const float* to_out_b = (const float*)d_in[7];
    const float* rpe      = (const float*)d_in[8];

    static __half* pV = nullptr;
    static __half* pOUTPRE = nullptr;
    static __half* pWVH = nullptr;
    static __half* pWOH = nullptr;
    if (!pV) {
        cudaGetSymbolAddress((void**)&pV, g_V);
        cudaGetSymbolAddress((void**)&pOUTPRE, g_OUTPRE);
        cudaGetSymbolAddress((void**)&pWVH, g_wvh);
        cudaGetSymbolAddress((void**)&pWOH, g_woh);
    }

    prep_kernel<<<1, 384>>>(query, Wk, Wk_bias, rpe);
    convw_kernel<<<128, 256>>>(to_v_w, to_out_w);

    dim3 ggrid((HW + BN - 1) / BN, CHID / BM, BATCH);  // (25, 3, 16)
    sgemm_v<<<ggrid, 128>>>(pWVH, to_v_b, x, pV);

    cost_kernel<<<(BATCH * HW) / 256, 256>>>(x);

    dwconv_kernel<<<BATCH * HEADS * 4, 256>>>();

    sgemm_out<<<ggrid, 128>>>(pWOH, to_out_b, pOUTPRE, (float*)d_out);
}

// round 14
// speedup vs baseline: 4.9277x; 1.0794x over previous
#include <cuda_runtime.h>
#include <cuda_fp16.h>
#include <math.h>
#include <stdint.h>

#define BATCH 16
#define CIN   192
#define CHID  384
#define HEADS 8
#define HDIM  48
#define IMG   56
#define HW    3136
#define KS    7

// ---------------- scratch ----------------
__device__ float g_qWkT[HEADS * CIN];
__device__ float g_biasq[HEADS];
__device__ float g_rpeexp[HEADS * 49];
__device__ __half g_wvh[CHID * CIN];                    // half to_v_w
__device__ __half g_woh[CHID * CHID];                   // half to_out_w
__device__ __half g_V[(size_t)BATCH * CHID * HW];       // 38.5 MB
__device__ float  g_COSTE[(size_t)BATCH * HEADS * HW];  // 1.6 MB
__device__ __half g_OUTPRE[(size_t)BATCH * CHID * HW];  // 38.5 MB

__device__ __forceinline__ uint32_t smem_u32(const void* p) {
    uint32_t a;
    asm("{ .reg .u64 t; cvta.to.shared.u64 t, %1; cvt.u32.u64 %0, t; }" : "=r"(a) : "l"(p));
    return a;
}
__device__ __forceinline__ uint32_t packh2(float x, float y) {
    __half2 h = __floats2half2_rn(x, y);
    return *reinterpret_cast<uint32_t*>(&h);
}

// ---------------- K0: prep ----------------
__global__ void prep_kernel(const float* __restrict__ query,
                            const float* __restrict__ Wk,
                            const float* __restrict__ Wk_bias,
                            const float* __restrict__ rpe) {
    __shared__ float sq[CHID];
    __shared__ float snorm[HEADS];
    int tid = threadIdx.x;
    float inv = 1.0f / (sqrtf((float)HDIM) + 1e-6f);
    if (tid < CHID) sq[tid] = query[tid] * inv;
    __syncthreads();
    if (tid < HEADS) {
        float s = 0.f;
        for (int d = 0; d < HDIM; d++) { float v = sq[tid * HDIM + d]; s += v * v; }
        snorm[tid] = sqrtf(s) + 1e-6f;
    }
    __syncthreads();
    if (tid < CHID) sq[tid] = sq[tid] / snorm[tid / HDIM];
    __syncthreads();
    for (int e = tid; e < HEADS * CIN; e += blockDim.x) {
        int h = e / CIN, D = e % CIN;
        float s = 0.f;
        #pragma unroll 8
        for (int d = 0; d < HDIM; d++)
            s += sq[h * HDIM + d] * Wk[(size_t)D * CHID + h * HDIM + d];
        g_qWkT[e] = s;
    }
    if (tid < HEADS) {
        float s = 0.f;
        for (int d = 0; d < HDIM; d++)
            s += Wk_bias[tid * HDIM + d] * sq[tid * HDIM + d];
        g_biasq[tid] = s;
    }
    for (int e = tid; e < HEADS * 49; e += blockDim.x)
        g_rpeexp[e] = expf(rpe[e]);
}

// ---------------- weight conversion ----------------
__global__ __launch_bounds__(256)
void convw_kernel(const float* __restrict__ wv, const float* __restrict__ wo) {
    int gid = blockIdx.x * 256 + threadIdx.x;
    int nth = gridDim.x * 256;
    for (int i = gid; i < CHID * CIN; i += nth) g_wvh[i] = __float2half_rn(wv[i]);
    for (int i = gid; i < CHID * CHID; i += nth) g_woh[i] = __float2half_rn(wo[i]);
}

// ---------------- shared GEMM config ----------------
#define BM 128
#define BN 128

// ---------------- GEMM1: half A(weights), fp32 B(x) -> half C (V) ----------
#define BK1 16
#define APB1 48
#define BPB 272
#define ASTG1 (BM * APB1)
#define BSTG1 (BK1 * BPB)

__global__ __launch_bounds__(128, 2)
void sgemm_v(const __half* __restrict__ A, const float* __restrict__ bias,
             const float* __restrict__ X, __half* __restrict__ C) {
    const int K = CIN;
    const int b  = blockIdx.z;
    const int m0 = blockIdx.y * BM;
    const int n0 = blockIdx.x * BN;
    const float* Xb = X + (size_t)b * K * HW;
    __half* Cb = C + (size_t)b * CHID * HW;

    __shared__ __align__(16) char sA[2][ASTG1];
    __shared__ __align__(16) char sB[2][BSTG1];

    const int tid  = threadIdx.x;
    const int warp = tid >> 5;
    const int lane = tid & 31;
    const int quad = lane >> 2;
    const int qi   = lane & 3;
    const int m_base = (warp & 1) * 64;
    const int n_base = (warp >> 1) * 64;

    const uint32_t uA = smem_u32(&sA[0][0]);
    const uint32_t uB = smem_u32(&sB[0][0]);
    const uint32_t aAddrBase = uA + (uint32_t)(m_base + (lane & 15)) * APB1 + (uint32_t)((lane >> 4) * 8) * 2;
    const uint32_t bAddrBase = uB + (uint32_t)(lane & 15) * BPB + (uint32_t)(n_base + (lane >> 4) * 8) * 2;

    float acc[4][8][4];
    #pragma unroll
    for (int i = 0; i < 4; i++)
        #pragma unroll
        for (int j = 0; j < 8; j++)
            #pragma unroll
            for (int r = 0; r < 4; r++) acc[i][j][r] = 0.f;

    uint4 aR[2];
    float4 bR[4];
    auto load_regs = [&](int k0) {
        #pragma unroll
        for (int p = 0; p < 2; p++) {
            int c = p * 128 + tid;
            int m = c >> 1, j = c & 1;
            aR[p] = *reinterpret_cast<const uint4*>(&A[(size_t)(m0 + m) * K + k0 + j * 8]);
        }
        #pragma unroll
        for (int p = 0; p < 4; p++) {
            int c = p * 128 + tid;
            int kr = c >> 5, nc = (c & 31) * 4;
            int col = n0 + nc; if (col > HW - 4) col = HW - 4;
            bR[p] = *reinterpret_cast<const float4*>(&Xb[(size_t)(k0 + kr) * HW + col]);
        }
    };
    auto store_stage = [&](int buf) {
        #pragma unroll
        for (int p = 0; p < 2; p++) {
            int c = p * 128 + tid;
            int m = c >> 1, j = c & 1;
            *reinterpret_cast<uint4*>(&sA[buf][m * APB1 + j * 16]) = aR[p];
        }
        #pragma unroll
        for (int p = 0; p < 4; p++) {
            int c = p * 128 + tid;
            int kr = c >> 5, nc = (c & 31) * 4;
            uint2 v = make_uint2(packh2(bR[p].x, bR[p].y), packh2(bR[p].z, bR[p].w));
            *reinterpret_cast<uint2*>(&sB[buf][kr * BPB + nc * 2]) = v;
        }
    };

    load_regs(0);
    store_stage(0);
    __syncthreads();

    const int T = K / BK1;
    for (int t = 0; t < T; t++) {
        const int buf = t & 1;
        if (t + 1 < T) load_regs((t + 1) * BK1);

        uint32_t af[4][4], bf[4][4];
        const uint32_t aOff = aAddrBase + (buf ? ASTG1 : 0);
        const uint32_t bOff = bAddrBase + (buf ? BSTG1 : 0);
        #pragma unroll
        for (int mt = 0; mt < 4; mt++)
            asm volatile("ldmatrix.sync.aligned.m8n8.x4.shared.b16 {%0,%1,%2,%3}, [%4];"
                : "=r"(af[mt][0]), "=r"(af[mt][1]), "=r"(af[mt][2]), "=r"(af[mt][3])
                : "r"(aOff + (uint32_t)(mt * 16) * APB1));
        #pragma unroll
        for (int j = 0; j < 4; j++)
            asm volatile("ldmatrix.sync.aligned.m8n8.x4.trans.shared.b16 {%0,%1,%2,%3}, [%4];"
                : "=r"(bf[j][0]), "=r"(bf[j][1]), "=r"(bf[j][2]), "=r"(bf[j][3])
                : "r"(bOff + (uint32_t)(j * 16) * 2));
        #pragma unroll
        for (int mt = 0; mt < 4; mt++)
            #pragma unroll
            for (int nt = 0; nt < 8; nt++) {
                const int j = nt >> 1, h = (nt & 1) * 2;
                asm volatile(
                    "mma.sync.aligned.m16n8k16.row.col.f32.f16.f16.f32 "
                    "{%0,%1,%2,%3}, {%4,%5,%6,%7}, {%8,%9}, {%0,%1,%2,%3};"
                    : "+f"(acc[mt][nt][0]), "+f"(acc[mt][nt][1]),
                      "+f"(acc[mt][nt][2]), "+f"(acc[mt][nt][3])
                    : "r"(af[mt][0]), "r"(af[mt][1]), "r"(af[mt][2]), "r"(af[mt][3]),
                      "r"(bf[j][h]), "r"(bf[j][h + 1]));
            }

        if (t + 1 < T) store_stage(1 - buf);
        __syncthreads();
    }

    #pragma unroll
    for (int mt = 0; mt < 4; mt++) {
        const int r = m0 + m_base + mt * 16 + quad;
        const float bi0 = bias[r];
        const float bi1 = bias[r + 8];
        #pragma unroll
        for (int nt = 0; nt < 8; nt++) {
            const int c = n0 + n_base + nt * 8 + qi * 2;
            if (c < HW) {
                __half2 v0 = __floats2half2_rn(acc[mt][nt][0] + bi0, acc[mt][nt][1] + bi0);
                __half2 v1 = __floats2half2_rn(acc[mt][nt][2] + bi1, acc[mt][nt][3] + bi1);
                *reinterpret_cast<__half2*>(&Cb[(size_t)r * HW + c]) = v0;
                *reinterpret_cast<__half2*>(&Cb[(size_t)(r + 8) * HW + c]) = v1;
            }
        }
    }
}

// ---------------- GEMM2: half A(weights), half B(OUTPRE) -> fp32 C ----------
#define BK2 32
#define APB2 80
#define ASTG2 (BM * APB2)
#define BSTG2 (BK2 * BPB)

__global__ __launch_bounds__(128, 2)
void sgemm_out(const __half* __restrict__ A, const float* __restrict__ bias,
               const __half* __restrict__ X, float* __restrict__ C) {
    const int K = CHID;
    const int b  = blockIdx.z;
    const int m0 = blockIdx.y * BM;
    const int n0 = blockIdx.x * BN;
    const __half* Xb = X + (size_t)b * K * HW;
    float* Cb = C + (size_t)b * CHID * HW;

    __shared__ __align__(16) char sA[2][ASTG2];
    __shared__ __align__(16) char sB[2][BSTG2];

    const int tid  = threadIdx.x;
    const int warp = tid >> 5;
    const int lane = tid & 31;
    const int quad = lane >> 2;
    const int qi   = lane & 3;
    const int m_base = (warp & 1) * 64;
    const int n_base = (warp >> 1) * 64;

    const uint32_t uA = smem_u32(&sA[0][0]);
    const uint32_t uB = smem_u32(&sB[0][0]);
    const uint32_t aAddrBase = uA + (uint32_t)(m_base + (lane & 15)) * APB2 + (uint32_t)((lane >> 4) * 8) * 2;
    const uint32_t bAddrBase = uB + (uint32_t)(lane & 15) * BPB + (uint32_t)(n_base + (lane >> 4) * 8) * 2;

    float acc[4][8][4];
    #pragma unroll
    for (int i = 0; i < 4; i++)
        #pragma unroll
        for (int j = 0; j < 8; j++)
            #pragma unroll
            for (int r = 0; r < 4; r++) acc[i][j][r] = 0.f;

    uint4 aR[4], bR[4];
    auto load_regs = [&](int k0) {
        #pragma unroll
        for (int p = 0; p < 4; p++) {
            int c = p * 128 + tid;
            int m = c >> 2, j = c & 3;
            aR[p] = *reinterpret_cast<const uint4*>(&A[(size_t)(m0 + m) * K + k0 + j * 8]);
        }
        #pragma unroll
        for (int p = 0; p < 4; p++) {
            int c = p * 128 + tid;
            int kr = c >> 4, nc = (c & 15) * 8;
            int col = n0 + nc; if (col > HW - 8) col = HW - 8;
            bR[p] = *reinterpret_cast<const uint4*>(&Xb[(size_t)(k0 + kr) * HW + col]);
        }
    };
    auto store_stage = [&](int buf) {
        #pragma unroll
        for (int p = 0; p < 4; p++) {
            int c = p * 128 + tid;
            int m = c >> 2, j = c & 3;
            *reinterpret_cast<uint4*>(&sA[buf][m * APB2 + j * 16]) = aR[p];
        }
        #pragma unroll
        for (int p = 0; p < 4; p++) {
            int c = p * 128 + tid;
            int kr = c >> 4, nc = (c & 15) * 8;
            *reinterpret_cast<uint4*>(&sB[buf][kr * BPB + nc * 2]) = bR[p];
        }
    };

    load_regs(0);
    store_stage(0);
    __syncthreads();

    const int T = K / BK2;
    for (int t = 0; t < T; t++) {
        const int buf = t & 1;
        if (t + 1 < T) load_regs((t + 1) * BK2);

        const uint32_t aOff = aAddrBase + (buf ? ASTG2 : 0);
        const uint32_t bOff = bAddrBase + (buf ? BSTG2 : 0);
        #pragma unroll
        for (int h = 0; h < 2; h++) {
            uint32_t af[4][4], bf[4][4];
            #pragma unroll
            for (int mt = 0; mt < 4; mt++)
                asm volatile("ldmatrix.sync.aligned.m8n8.x4.shared.b16 {%0,%1,%2,%3}, [%4];"
                    : "=r"(af[mt][0]), "=r"(af[mt][1]), "=r"(af[mt][2]), "=r"(af[mt][3])
                    : "r"(aOff + (uint32_t)(mt * 16) * APB2 + (uint32_t)(h * 32)));
            #pragma unroll
            for (int j = 0; j < 4; j++)
                asm volatile("ldmatrix.sync.aligned.m8n8.x4.trans.shared.b16 {%0,%1,%2,%3}, [%4];"
                    : "=r"(bf[j][0]), "=r"(bf[j][1]), "=r"(bf[j][2]), "=r"(bf[j][3])
                    : "r"(bOff + (uint32_t)(j * 16) * 2 + (uint32_t)(h * 16) * BPB));
            #pragma unroll
            for (int mt = 0; mt < 4; mt++)
                #pragma unroll
                for (int nt = 0; nt < 8; nt++) {
                    const int j = nt >> 1, hh = (nt & 1) * 2;
                    asm volatile(
                        "mma.sync.aligned.m16n8k16.row.col.f32.f16.f16.f32 "
                        "{%0,%1,%2,%3}, {%4,%5,%6,%7}, {%8,%9}, {%0,%1,%2,%3};"
                        : "+f"(acc[mt][nt][0]), "+f"(acc[mt][nt][1]),
                          "+f"(acc[mt][nt][2]), "+f"(acc[mt][nt][3])
                        : "r"(af[mt][0]), "r"(af[mt][1]), "r"(af[mt][2]), "r"(af[mt][3]),
                          "r"(bf[j][hh]), "r"(bf[j][hh + 1]));
                }
        }

        if (t + 1 < T) store_stage(1 - buf);
        __syncthreads();
    }

    #pragma unroll
    for (int mt = 0; mt < 4; mt++) {
        const int r = m0 + m_base + mt * 16 + quad;
        const float bi0 = bias[r];
        const float bi1 = bias[r + 8];
        #pragma unroll
        for (int nt = 0; nt < 8; nt++) {
            const int c = n0 + n_base + nt * 8 + qi * 2;
            if (c < HW) {
                float2 v0 = make_float2(acc[mt][nt][0] + bi0, acc[mt][nt][1] + bi0);
                float2 v1 = make_float2(acc[mt][nt][2] + bi1, acc[mt][nt][3] + bi1);
                *reinterpret_cast<float2*>(&Cb[(size_t)r * HW + c]) = v0;
                *reinterpret_cast<float2*>(&Cb[(size_t)(r + 8) * HW + c]) = v1;
            }
        }
    }
}

// ---------------- cost kernel v2: split-D, 512 threads ----------------
// block = 128 pixels (flattened over BATCH*HW); 4 D-groups of 48 channels.
__global__ __launch_bounds__(512)
void cost_kernel(const float* __restrict__ x) {
    __shared__ float4 sW4[HEADS * CIN / 4];   // 6 KB
    __shared__ float sb[HEADS];
    __shared__ float part[4][HEADS][128];     // 16 KB

    const int tid = threadIdx.x;
    const int g   = tid >> 7;        // D-group 0..3
    const int px  = tid & 127;       // pixel in block

    const float4* gW4 = reinterpret_cast<const float4*>(g_qWkT);
    for (int i = tid; i < HEADS * CIN / 4; i += 512) sW4[i] = gW4[i];
    if (tid < HEADS) sb[tid] = g_biasq[tid];
    __syncthreads();

    const int gpix = blockIdx.x * 128 + px;
    const int b = gpix / HW, hw = gpix % HW;
    const float* xb = x + (size_t)b * CIN * HW + hw;

    float acc[HEADS] = {};
    const int d0 = g * (CIN / 4 / 4);   // group base in float4 units (12 per group)
    #pragma unroll 4
    for (int D4 = d0; D4 < d0 + 12; D4++) {
        float x0 = xb[(size_t)(D4 * 4 + 0) * HW];
        float x1 = xb[(size_t)(D4 * 4 + 1) * HW];
        float x2 = xb[(size_t)(D4 * 4 + 2) * HW];
        float x3 = xb[(size_t)(D4 * 4 + 3) * HW];
        #pragma unroll
        for (int h = 0; h < HEADS; h++) {
            float4 w = sW4[h * (CIN / 4) + D4];
            acc[h] += x0 * w.x + x1 * w.y + x2 * w.z + x3 * w.w;
        }
    }
    #pragma unroll
    for (int h = 0; h < HEADS; h++) part[g][h][px] = acc[h];
    __syncthreads();

    if (tid < 128) {
        float* cb = g_COSTE + (size_t)b * HEADS * HW + hw;
        #pragma unroll
        for (int h = 0; h < HEADS; h++) {
            float s = part[0][h][px] + part[1][h][px] + part[2][h][px] + part[3][h][px];
            cb[(size_t)h * HW] = expf(s + sb[h]);
        }
    }
}

// ---------------- dwconv kernel (vectorized windows) ----------------
#define DP 68

__global__ __launch_bounds__(256)
void dwconv_kernel() {
    const int bidx = blockIdx.x;
    const int cg = bidx & 3;
    const int head = (bidx >> 2) & 7;
    const int b = bidx >> 5;

    __shared__ __align__(16) float sc[62 * DP];
    __shared__ __align__(16) float scv[62 * DP];

    const int tid = threadIdx.x;

    float wr[49];
    #pragma unroll
    for (int i = 0; i < 49; i++) wr[i] = g_rpeexp[head * 49 + i];

    const float* cp = g_COSTE + ((size_t)b * HEADS + head) * HW;
    for (int i = tid; i < 62 * DP; i += 256) {
        int r = i / DP, c = i % DP;
        int y = r - 3, x = c - 4;
        float v = 0.f;
        if ((unsigned)y < 56u && (unsigned)x < 56u) v = cp[y * 56 + x];
        sc[i] = v;
        scv[i] = 0.f;
    }
    __syncthreads();

    const int y0 = (tid / 14) * 4;
    const int x0 = (tid % 14) * 4;
    const bool active = tid < 196;

    float4 rden[4];
    if (active) {
        float acc[4][4] = {};
        #pragma unroll
        for (int i = 0; i < 10; i++) {
            const float* base = &sc[(y0 + i) * DP + x0];
            float4 q0 = *reinterpret_cast<const float4*>(base);
            float4 q1 = *reinterpret_cast<const float4*>(base + 4);
            float4 q2 = *reinterpret_cast<const float4*>(base + 8);
            float r[12] = {q0.x, q0.y, q0.z, q0.w, q1.x, q1.y, q1.z, q1.w,
                           q2.x, q2.y, q2.z, q2.w};
            #pragma unroll
            for (int oy = 0; oy < 4; oy++) {
                const int wi = i - oy;
                if (wi >= 0 && wi < 7) {
                    #pragma unroll
                    for (int j = 0; j < 7; j++) {
                        float wv = wr[wi * 7 + j];
                        acc[oy][0] += wv * r[j + 1];
                        acc[oy][1] += wv * r[j + 2];
                        acc[oy][2] += wv * r[j + 3];
                        acc[oy][3] += wv * r[j + 4];
                    }
                }
            }
        }
        #pragma unroll
        for (int oy = 0; oy < 4; oy++)
            rden[oy] = make_float4(1.f / acc[oy][0], 1.f / acc[oy][1],
                                   1.f / acc[oy][2], 1.f / acc[oy][3]);
    }

    for (int c = 0; c < 12; c++) {
        const int ch = head * HDIM + cg * 12 + c;
        const __half* vp = g_V + ((size_t)b * CHID + ch) * HW;
        __syncthreads();
        for (int i = tid; i < 784; i += 256) {
            int y = i / 14, c4 = (i % 14) * 4;
            uint2 raw = *reinterpret_cast<const uint2*>(&vp[y * 56 + c4]);
            float2 f0 = __half22float2(*reinterpret_cast<__half2*>(&raw.x));
            float2 f1 = __half22float2(*reinterpret_cast<__half2*>(&raw.y));
            float4 s = *reinterpret_cast<const float4*>(&sc[(y + 3) * DP + 4 + c4]);
            float4 o = make_float4(f0.x * s.x, f0.y * s.y, f1.x * s.z, f1.y * s.w);
            *reinterpret_cast<float4*>(&scv[(y + 3) * DP + 4 + c4]) = o;
        }
        __syncthreads();
        if (active) {
            float acc[4][4] = {};
            #pragma unroll
            for (int i = 0; i < 10; i++) {
                const float* base = &scv[(y0 + i) * DP + x0];
                float4 q0 = *reinterpret_cast<const float4*>(base);
                float4 q1 = *reinterpret_cast<const float4*>(base + 4);
                float4 q2 = *reinterpret_cast<const float4*>(base + 8);
                float r[12] = {q0.x, q0.y, q0.z, q0.w, q1.x, q1.y, q1.z, q1.w,
                               q2.x, q2.y, q2.z, q2.w};
                #pragma unroll
                for (int oy = 0; oy < 4; oy++) {
                    const int wi = i - oy;
                    if (wi >= 0 && wi < 7) {
                        #pragma unroll
                        for (int j = 0; j < 7; j++) {
                            float wv = wr[wi * 7 + j];
                            acc[oy][0] += wv * r[j + 1];
                            acc[oy][1] += wv * r[j + 2];
                            acc[oy][2] += wv * r[j + 3];
                            acc[oy][3] += wv * r[j + 4];
                        }
                    }
                }
            }
            __half* op = g_OUTPRE + ((size_t)b * CHID + ch) * HW;
            #pragma unroll
            for (int oy = 0; oy < 4; oy++) {
                __half2 o0 = __floats2half2_rn(acc[oy][0] * rden[oy].x, acc[oy][1] * rden[oy].y);
                __half2 o1 = __floats2half2_rn(acc[oy][2] * rden[oy].z, acc[oy][3] * rden[oy].w);
                uint2 pk = make_uint2(*reinterpret_cast<uint32_t*>(&o0),
                                      *reinterpret_cast<uint32_t*>(&o1));
                *reinterpret_cast<uint2*>(&op[(y0 + oy) * 56 + x0]) = pk;
            }
        }
    }
}

// ---------------- launch ----------------
extern "C" void kernel_launch(void* const* d_in, const int* in_sizes, int n_in,
                              void* d_out, int out_size) {
    const float* x        = (const float*)d_in[0];
    const float* query    = (const float*)d_in[1];
    const float* Wk       = (const float*)d_in[2];
    const float* Wk_bias  = (const float*)d_in[3];
    const float* to_v_w   = (const float*)d_in[4];
    const float* to_v_b   = (const float*)d_in[5];
    const float* to_out_w = (const float*)d_in[6];
    const float* to_out_b = (const float*)d_in[7];
    const float* rpe      = (const float*)d_in[8];

    static __half* pV = nullptr;
    static __half* pOUTPRE = nullptr;
    static __half* pWVH = nullptr;
    static __half* pWOH = nullptr;
    static cudaStream_t s2 = nullptr;
    static cudaEvent_t eFork = nullptr, eJoin = nullptr;
    if (!pV) {
        cudaGetSymbolAddress((void**)&pV, g_V);
        cudaGetSymbolAddress((void**)&pOUTPRE, g_OUTPRE);
        cudaGetSymbolAddress((void**)&pWVH, g_wvh);
        cudaGetSymbolAddress((void**)&pWOH, g_woh);
        cudaStreamCreateWithFlags(&s2, cudaStreamNonBlocking);
        cudaEventCreateWithFlags(&eFork, cudaEventDisableTiming);
        cudaEventCreateWithFlags(&eJoin, cudaEventDisableTiming);
    }

    prep_kernel<<<1, 384>>>(query, Wk, Wk_bias, rpe);
    convw_kernel<<<128, 256>>>(to_v_w, to_out_w);

    // fork: cost (needs prep) runs concurrently with GEMM1 (needs convw)
    cudaEventRecord(eFork, 0);
    cudaStreamWaitEvent(s2, eFork, 0);

    dim3 ggrid((HW + BN - 1) / BN, CHID / BM, BATCH);  // (25, 3, 16)
    sgemm_v<<<ggrid, 128>>>(pWVH, to_v_b, x, pV);

    cost_kernel<<<(BATCH * HW) / 128, 512, 0, s2>>>(x);
    cudaEventRecord(eJoin, s2);
    cudaStreamWaitEvent(0, eJoin, 0);

    dwconv_kernel<<<BATCH * HEADS * 4, 256>>>();

    sgemm_out<<<ggrid, 128>>>(pWOH, to_out_b, pOUTPRE, (float*)d_out);
}